// round 13
// baseline (speedup 1.0000x reference)
#include <cuda_runtime.h>
#include <cuda_fp16.h>
#include <cstdint>

#define B_ 4
#define D_ 1024
#define S_ 2048

// ---------------------------------------------------------------------------
// Scratch. Each tensor X: Xh = fp16(X), X8 = s8(X/sh), Xl8 = s8((X-Xh)/sl)
// with sh = M'/127, sl = M'*2^-12/127, M' = per-tensor power-of-2 bound.
// ---------------------------------------------------------------------------
__device__ __half   g_xTh[(size_t)B_ * S_ * D_];
__device__ int8_t   g_xT8 [(size_t)B_ * S_ * D_];
__device__ int8_t   g_xTl8[(size_t)B_ * S_ * D_];
__device__ __half   g_Wqh[(size_t)D_ * D_];
__device__ int8_t   g_Wq8[(size_t)D_ * D_], g_Wql8[(size_t)D_ * D_];
__device__ __half   g_Wkh[(size_t)D_ * D_];
__device__ int8_t   g_Wk8[(size_t)D_ * D_], g_Wkl8[(size_t)D_ * D_];
__device__ __half   g_Wvh[(size_t)D_ * D_];
__device__ int8_t   g_Wv8[(size_t)D_ * D_], g_Wvl8[(size_t)D_ * D_];
__device__ __half   g_Qh[(size_t)B_ * S_ * D_];
__device__ int8_t   g_Q8[(size_t)B_ * S_ * D_], g_Ql8[(size_t)B_ * S_ * D_];
__device__ __half   g_Kh[(size_t)B_ * S_ * D_];
__device__ int8_t   g_K8[(size_t)B_ * S_ * D_], g_Kl8[(size_t)B_ * S_ * D_];
__device__ __half   g_Vh[(size_t)B_ * D_ * S_];
__device__ int8_t   g_V8[(size_t)B_ * D_ * S_], g_Vl8[(size_t)B_ * D_ * S_];
__device__ float    g_S [(size_t)B_ * S_ * S_];
__device__ __half   g_Ph[(size_t)B_ * S_ * S_];
__device__ int8_t   g_P8[(size_t)B_ * S_ * S_], g_Pl8[(size_t)B_ * S_ * S_];

// ---------------------------------------------------------------------------
// PTX helpers
// ---------------------------------------------------------------------------
__device__ __forceinline__ uint32_t smem_to_u32(const void* p) {
    uint32_t a;
    asm("{ .reg .u64 t; cvta.to.shared.u64 t, %1; cvt.u32.u64 %0, t; }"
        : "=r"(a) : "l"(p));
    return a;
}

#define CP_ASYNC16(dst_u32, src_ptr) \
    asm volatile("cp.async.cg.shared.global [%0], [%1], 16;" \
                 :: "r"(dst_u32), "l"(src_ptr) : "memory")

#define CP_COMMIT() asm volatile("cp.async.commit_group;" ::: "memory")

#define CP_WAIT(N) asm volatile("cp.async.wait_group %0;" :: "n"(N) : "memory")

#define LDSM4(R, addr) \
    asm volatile("ldmatrix.sync.aligned.m8n8.x4.shared.b16 {%0,%1,%2,%3}, [%4];" \
                 : "=r"((R)[0]), "=r"((R)[1]), "=r"((R)[2]), "=r"((R)[3]) \
                 : "r"(addr))

#define MMA16816(D, A, Bf) \
    asm("mma.sync.aligned.m16n8k16.row.col.f32.f16.f16.f32 " \
        "{%0,%1,%2,%3}, {%4,%5,%6,%7}, {%8,%9}, {%0,%1,%2,%3};" \
        : "+f"((D)[0]), "+f"((D)[1]), "+f"((D)[2]), "+f"((D)[3]) \
        : "r"((A)[0]), "r"((A)[1]), "r"((A)[2]), "r"((A)[3]), \
          "r"((Bf)[0]), "r"((Bf)[1]))

#define MMAI8(D, A, Bf) \
    asm("mma.sync.aligned.m16n8k32.row.col.s32.s8.s8.s32 " \
        "{%0,%1,%2,%3}, {%4,%5,%6,%7}, {%8,%9}, {%0,%1,%2,%3};" \
        : "+r"((D)[0]), "+r"((D)[1]), "+r"((D)[2]), "+r"((D)[3]) \
        : "r"((A)[0]), "r"((A)[1]), "r"((A)[2]), "r"((A)[3]), \
          "r"((Bf)[0]), "r"((Bf)[1]))

__device__ __forceinline__ int8_t q8(float v, float s_inv) {
    int i = __float2int_rn(v * s_inv);
    i = max(-127, min(127, i));
    return (int8_t)i;
}

// 3-form split: fp16 hi; s8 of value (scale inv hi_inv); s8 of residual
// (scale inv lo_inv = hi_inv * 4096).
__device__ __forceinline__ void split3i(float v, float hi_inv, float lo_inv,
                                        __half& h, int8_t& f8, int8_t& fl8) {
    h = __float2half_rn(v);
    f8 = q8(v, hi_inv);
    fl8 = q8(v - __half2float(h), lo_inv);
}

// ---------------------------------------------------------------------------
// GEMM: D[m,n] = sum_k A[m,k]*B[n,k]
//   acc_hi += Ah(fp16)*Bh(fp16)            [2x m16n8k16]
//   acc_lo += A8l*B8 + A8*B8l  (s8, s32)   [2x m16n8k32, ONE accumulator]
//   v = acc_hi + (float)acc_lo * CSCALE    (CSCALE = sAl*sBh = sAh*sBl)
// MODE 0: 3-form out +bias[n]; MODE 1: 3-form out +bias[m];
// MODE 2: fp32 out * 1/32; MODE 3: fp32 out
// CTA 128x64, 8 warps (4m x 2n), warp tile 32x32. 3-stage cp.async.
// fp16 pitch 80B; int8 pitch 48B. Layout identical to round-11 (proven).
// ---------------------------------------------------------------------------
#define SM_AH  0
#define SM_BH  10240
#define SM_A8  15360
#define SM_AL8 21504
#define SM_B8  27648
#define SM_BL8 30720
#define STAGE_BYTES 33792
#define NSTAGE 3

template <int KEL, int MODE>
__global__ __launch_bounds__(256, 2) void tc_gemm(
    const __half* __restrict__ Ah, const int8_t* __restrict__ A8,
    const int8_t* __restrict__ Al8, size_t sA,
    const __half* __restrict__ Bh, const int8_t* __restrict__ B8,
    const int8_t* __restrict__ Bl8, size_t sB,
    const float* __restrict__ bias, float cscale,
    float* __restrict__ outF,
    __half* __restrict__ outH, int8_t* __restrict__ out8,
    int8_t* __restrict__ outL8,
    size_t sO, int ldo)
{
    extern __shared__ char smem[];
    const uint32_t smem_base = smem_to_u32(smem);
    const int tid = threadIdx.x;
    const int wid = tid >> 5;
    const int lid = tid & 31;
    const int wm = wid >> 1;
    const int wn = wid & 1;
    const int b = blockIdx.z;
    const int m0 = blockIdx.y * 128;
    const int n0 = blockIdx.x * 64;

    Ah += (size_t)b * sA; A8 += (size_t)b * sA; Al8 += (size_t)b * sA;
    Bh += (size_t)b * sB; B8 += (size_t)b * sB; Bl8 += (size_t)b * sB;

    float acc_hi[2][4][4];
    int   acc_lo[2][4][4];
    #pragma unroll
    for (int i = 0; i < 2; ++i)
        #pragma unroll
        for (int j = 0; j < 4; ++j)
            #pragma unroll
            for (int k = 0; k < 4; ++k) { acc_hi[i][j][k] = 0.f; acc_lo[i][j][k] = 0; }

    constexpr int NC = KEL / 32;

    auto load_chunk = [&](int c) {
        const int koff = c * 32;
        const uint32_t sb = smem_base + (uint32_t)(c % NSTAGE) * STAGE_BYTES;
        #pragma unroll
        for (int i = 0; i < 2; ++i) {               // fp16 Ah
            const int idx = tid + i * 256;
            const int row = idx >> 2, c16 = idx & 3;
            CP_ASYNC16(sb + SM_AH + row * 80 + c16 * 16,
                       Ah + (size_t)(m0 + row) * KEL + koff + c16 * 8);
        }
        {                                           // fp16 Bh
            const int row = tid >> 2, c16 = tid & 3;
            CP_ASYNC16(sb + SM_BH + row * 80 + c16 * 16,
                       Bh + (size_t)(n0 + row) * KEL + koff + c16 * 8);
        }
        {                                           // s8 A8 + Al8
            const int row = tid >> 1, c16 = tid & 1;
            const size_t ga = (size_t)(m0 + row) * KEL + koff + c16 * 16;
            CP_ASYNC16(sb + SM_A8 + row * 48 + c16 * 16, A8 + ga);
            CP_ASYNC16(sb + SM_AL8 + row * 48 + c16 * 16, Al8 + ga);
        }
        {                                           // s8 B8 / Bl8
            const int t = tid & 127;
            const int row = t >> 1, c16 = t & 1;
            const size_t gb = (size_t)(n0 + row) * KEL + koff + c16 * 16;
            if (tid < 128)
                CP_ASYNC16(sb + SM_B8 + row * 48 + c16 * 16, B8 + gb);
            else
                CP_ASYNC16(sb + SM_BL8 + row * 48 + c16 * 16, Bl8 + gb);
        }
        CP_COMMIT();
    };

    load_chunk(0);
    load_chunk(1);

    const int rowA = wm * 32 + (lid & 15);
    const int rowB = wn * 32 + (lid & 15);
    const uint32_t kb = (uint32_t)((lid >> 4) * 16);

    const int g = lid >> 3;
    const uint32_t a8_lane = (uint32_t)((((g & 1) * 8) + (lid & 7)) * 48 + (g >> 1) * 16);
    const uint32_t b8_lane = (uint32_t)((((g >> 1) * 8) + (lid & 7)) * 48 + (g & 1) * 16);

    #pragma unroll 1
    for (int c = 0; c < NC; ++c) {
        if (c + 1 < NC) { CP_WAIT(1); } else { CP_WAIT(0); }
        __syncthreads();
        if (c + 2 < NC) load_chunk(c + 2);

        const uint32_t sb = smem_base + (uint32_t)(c % NSTAGE) * STAGE_BYTES;

        // ---- fp16 hi phase ----
        #pragma unroll
        for (int ks = 0; ks < 2; ++ks) {
            const uint32_t kbyte = (uint32_t)(ks * 32) + kb;
            uint32_t ah[2][4];
            #pragma unroll
            for (int mt = 0; mt < 2; ++mt)
                LDSM4(ah[mt], sb + SM_AH + (uint32_t)((rowA + mt * 16) * 80) + kbyte);
            uint32_t bh[4][2];
            #pragma unroll
            for (int np = 0; np < 2; ++np) {
                uint32_t t4[4];
                LDSM4(t4, sb + SM_BH + (uint32_t)((rowB + np * 16) * 80) + kbyte);
                bh[2 * np][0] = t4[0]; bh[2 * np][1] = t4[2];
                bh[2 * np + 1][0] = t4[1]; bh[2 * np + 1][1] = t4[3];
            }
            #pragma unroll
            for (int mt = 0; mt < 2; ++mt)
                #pragma unroll
                for (int nt = 0; nt < 4; ++nt)
                    MMA16816(acc_hi[mt][nt], ah[mt], bh[nt]);
        }

        // ---- int8 correction phase: acc_lo += A8l*B8 + A8*B8l ----
        {
            uint32_t a8h[2][4], a8l[2][4];
            #pragma unroll
            for (int mt = 0; mt < 2; ++mt) {
                const uint32_t base = (uint32_t)((wm * 32 + mt * 16) * 48) + a8_lane;
                LDSM4(a8h[mt], sb + SM_A8 + base);
                LDSM4(a8l[mt], sb + SM_AL8 + base);
            }
            uint32_t b8h[4][2], b8l[4][2];
            #pragma unroll
            for (int np = 0; np < 2; ++np) {
                const uint32_t base = (uint32_t)((wn * 32 + np * 16) * 48) + b8_lane;
                uint32_t t4[4];
                LDSM4(t4, sb + SM_B8 + base);
                b8h[2 * np][0] = t4[0]; b8h[2 * np][1] = t4[1];
                b8h[2 * np + 1][0] = t4[2]; b8h[2 * np + 1][1] = t4[3];
                LDSM4(t4, sb + SM_BL8 + base);
                b8l[2 * np][0] = t4[0]; b8l[2 * np][1] = t4[1];
                b8l[2 * np + 1][0] = t4[2]; b8l[2 * np + 1][1] = t4[3];
            }
            #pragma unroll
            for (int mt = 0; mt < 2; ++mt)
                #pragma unroll
                for (int nt = 0; nt < 4; ++nt)
                    MMAI8(acc_lo[mt][nt], a8l[mt], b8h[nt]);
            #pragma unroll
            for (int mt = 0; mt < 2; ++mt)
                #pragma unroll
                for (int nt = 0; nt < 4; ++nt)
                    MMAI8(acc_lo[mt][nt], a8h[mt], b8l[nt]);
        }
    }

    // ---- epilogue ----
    const int gq = lid >> 2, t4i = lid & 3;
    // Q/K/V outputs use M'=4: hi_inv = 127/4, lo_inv = 127*4096/4
    const float OH_INV = 31.75f, OL_INV = 130048.0f;
    #pragma unroll
    for (int mt = 0; mt < 2; ++mt) {
        const int m = m0 + wm * 32 + mt * 16 + gq;
        float bm0 = 0.f, bm8 = 0.f;
        if (MODE == 1) { bm0 = bias[m]; bm8 = bias[m + 8]; }
        #pragma unroll
        for (int nt = 0; nt < 4; ++nt) {
            const int n = n0 + wn * 32 + nt * 8 + 2 * t4i;
            float v0 = acc_hi[mt][nt][0] + (float)acc_lo[mt][nt][0] * cscale;
            float v1 = acc_hi[mt][nt][1] + (float)acc_lo[mt][nt][1] * cscale;
            float v2 = acc_hi[mt][nt][2] + (float)acc_lo[mt][nt][2] * cscale;
            float v3 = acc_hi[mt][nt][3] + (float)acc_lo[mt][nt][3] * cscale;
            if (MODE == 0) {
                const float bn0 = bias[n], bn1 = bias[n + 1];
                v0 += bn0; v1 += bn1; v2 += bn0; v3 += bn1;
            } else if (MODE == 1) {
                v0 += bm0; v1 += bm0; v2 += bm8; v3 += bm8;
            } else if (MODE == 2) {
                v0 *= 0.03125f; v1 *= 0.03125f; v2 *= 0.03125f; v3 *= 0.03125f;
            }
            if (MODE == 0 || MODE == 1) {
                __half h0, h1; int8_t f0, f1, l0, l1;
                const size_t o0 = (size_t)b * sO + (size_t)m * ldo + n;
                split3i(v0, OH_INV, OL_INV, h0, f0, l0);
                split3i(v1, OH_INV, OL_INV, h1, f1, l1);
                { __half2 hh; hh.x = h0; hh.y = h1;
                  *(__half2*)(outH + o0) = hh;
                  char2 u8; u8.x = f0; u8.y = f1; *(char2*)(out8 + o0) = u8;
                  char2 ul; ul.x = l0; ul.y = l1; *(char2*)(outL8 + o0) = ul; }
                const size_t o8 = (size_t)b * sO + (size_t)(m + 8) * ldo + n;
                split3i(v2, OH_INV, OL_INV, h0, f0, l0);
                split3i(v3, OH_INV, OL_INV, h1, f1, l1);
                { __half2 hh; hh.x = h0; hh.y = h1;
                  *(__half2*)(outH + o8) = hh;
                  char2 u8; u8.x = f0; u8.y = f1; *(char2*)(out8 + o8) = u8;
                  char2 ul; ul.x = l0; ul.y = l1; *(char2*)(outL8 + o8) = ul; }
            } else {
                float2 f0; f0.x = v0; f0.y = v1;
                float2 f8; f8.x = v2; f8.y = v3;
                *(float2*)(outF + (size_t)b * sO + (size_t)m * ldo + n) = f0;
                *(float2*)(outF + (size_t)b * sO + (size_t)(m + 8) * ldo + n) = f8;
            }
        }
    }
}

// ---------------------------------------------------------------------------
// Weights: M' = 2^-5. hi_inv = 127*32, lo_inv = 127*4096*32
// ---------------------------------------------------------------------------
__global__ __launch_bounds__(256) void wsplit3_kernel(
    const float* __restrict__ w0, const float* __restrict__ w1,
    const float* __restrict__ w2,
    __half* __restrict__ h0, int8_t* __restrict__ f0, int8_t* __restrict__ l0,
    __half* __restrict__ h1, int8_t* __restrict__ f1, int8_t* __restrict__ l1,
    __half* __restrict__ h2, int8_t* __restrict__ f2, int8_t* __restrict__ l2)
{
    const int which = blockIdx.y;
    const float* w = (which == 0) ? w0 : (which == 1) ? w1 : w2;
    __half* h = (which == 0) ? h0 : (which == 1) ? h1 : h2;
    int8_t* f = (which == 0) ? f0 : (which == 1) ? f1 : f2;
    int8_t* l = (which == 0) ? l0 : (which == 1) ? l1 : l2;
    const int n = D_ * D_;
    const float HI = 127.0f * 32.0f, LO = 127.0f * 4096.0f * 32.0f;
    for (int i = blockIdx.x * 256 + threadIdx.x; i < n; i += gridDim.x * 256) {
        __half hi; int8_t v8, vl8;
        split3i(w[i], HI, LO, hi, v8, vl8);
        h[i] = hi; f[i] = v8; l[i] = vl8;
    }
}

// ---------------------------------------------------------------------------
// x transpose+split: M' = 8. hi_inv = 127/8, lo_inv = 127*512
// ---------------------------------------------------------------------------
__global__ __launch_bounds__(256) void xpose_split_kernel(const float* __restrict__ x)
{
    __shared__ float t[32][33];
    const int b = blockIdx.z;
    const int d0 = blockIdx.y * 32;
    const int s0 = blockIdx.x * 32;
    const int tx = threadIdx.x & 31;
    const int ty = threadIdx.x >> 5;
    const float* X = x + (size_t)b * D_ * S_;
    const float HI = 127.0f / 8.0f, LO = 127.0f * 512.0f;

    #pragma unroll
    for (int i = 0; i < 4; ++i)
        t[ty + i * 8][tx] = X[(size_t)(d0 + ty + i * 8) * S_ + s0 + tx];
    __syncthreads();
    #pragma unroll
    for (int i = 0; i < 4; ++i) {
        const int s = s0 + ty + i * 8;
        const int d = d0 + tx;
        const float v = t[tx][ty + i * 8];
        __half hi; int8_t v8, vl8;
        split3i(v, HI, LO, hi, v8, vl8);
        const size_t idx = (size_t)b * S_ * D_ + (size_t)s * D_ + d;
        g_xTh[idx] = hi;
        g_xT8[idx] = v8;
        g_xTl8[idx] = vl8;
    }
}

// ---------------------------------------------------------------------------
// softmax: P in [0,1], M' = 1. hi_inv = 127, lo_inv = 127*4096
// ---------------------------------------------------------------------------
__global__ __launch_bounds__(256) void softmax_split_kernel()
{
    const size_t row = blockIdx.x;
    const float* __restrict__ p = g_S + row * S_;
    __half* __restrict__ ph = g_Ph + row * S_;
    int8_t* __restrict__ p8 = g_P8 + row * S_;
    int8_t* __restrict__ pl8 = g_Pl8 + row * S_;
    const int tid = threadIdx.x;
    const float HI = 127.0f, LO = 127.0f * 4096.0f;

    float v[8];
    #pragma unroll
    for (int i = 0; i < 8; ++i) v[i] = p[i * 256 + tid];

    float m = v[0];
    #pragma unroll
    for (int i = 1; i < 8; ++i) m = fmaxf(m, v[i]);

    __shared__ float red[8];
    #pragma unroll
    for (int o = 16; o > 0; o >>= 1)
        m = fmaxf(m, __shfl_xor_sync(0xffffffffu, m, o));
    if ((tid & 31) == 0) red[tid >> 5] = m;
    __syncthreads();
    m = red[0];
    #pragma unroll
    for (int i = 1; i < 8; ++i) m = fmaxf(m, red[i]);
    __syncthreads();

    float s = 0.f;
    #pragma unroll
    for (int i = 0; i < 8; ++i) { v[i] = expf(v[i] - m); s += v[i]; }
    #pragma unroll
    for (int o = 16; o > 0; o >>= 1)
        s += __shfl_xor_sync(0xffffffffu, s, o);
    if ((tid & 31) == 0) red[tid >> 5] = s;
    __syncthreads();
    s = 0.f;
    #pragma unroll
    for (int i = 0; i < 8; ++i) s += red[i];

    const float inv = 1.0f / s;
    #pragma unroll
    for (int i = 0; i < 8; ++i) {
        __half hi; int8_t v8, vl8;
        split3i(v[i] * inv, HI, LO, hi, v8, vl8);
        ph[i * 256 + tid] = hi;
        p8[i * 256 + tid] = v8;
        pl8[i * 256 + tid] = vl8;
    }
}

// ---------------------------------------------------------------------------
extern "C" void kernel_launch(void* const* d_in, const int* in_sizes, int n_in,
                              void* d_out, int out_size)
{
    const float* x  = (const float*)d_in[0];
    const float* Wq = (const float*)d_in[1];
    const float* bq = (const float*)d_in[2];
    const float* Wk = (const float*)d_in[3];
    const float* bk = (const float*)d_in[4];
    const float* Wv = (const float*)d_in[5];
    const float* bv = (const float*)d_in[6];
    float* out = (float*)d_out;

    const int SMEM_SZ = NSTAGE * STAGE_BYTES;   // 101376

    cudaFuncSetAttribute(tc_gemm<1024, 0>, cudaFuncAttributeMaxDynamicSharedMemorySize, SMEM_SZ);
    cudaFuncSetAttribute(tc_gemm<1024, 1>, cudaFuncAttributeMaxDynamicSharedMemorySize, SMEM_SZ);
    cudaFuncSetAttribute(tc_gemm<1024, 2>, cudaFuncAttributeMaxDynamicSharedMemorySize, SMEM_SZ);
    cudaFuncSetAttribute(tc_gemm<2048, 3>, cudaFuncAttributeMaxDynamicSharedMemorySize, SMEM_SZ);

    __half *xTh, *Wqh, *Wkh, *Wvh, *Qh, *Kh, *Vh, *Ph;
    int8_t *xT8, *xTl8, *Wq8, *Wql8, *Wk8, *Wkl8, *Wv8, *Wvl8;
    int8_t *Q8, *Ql8, *K8, *Kl8, *V8, *Vl8, *P8, *Pl8;
    float* Sc;
    cudaGetSymbolAddress((void**)&xTh, g_xTh);
    cudaGetSymbolAddress((void**)&xT8, g_xT8);
    cudaGetSymbolAddress((void**)&xTl8, g_xTl8);
    cudaGetSymbolAddress((void**)&Wqh, g_Wqh);
    cudaGetSymbolAddress((void**)&Wq8, g_Wq8);
    cudaGetSymbolAddress((void**)&Wql8, g_Wql8);
    cudaGetSymbolAddress((void**)&Wkh, g_Wkh);
    cudaGetSymbolAddress((void**)&Wk8, g_Wk8);
    cudaGetSymbolAddress((void**)&Wkl8, g_Wkl8);
    cudaGetSymbolAddress((void**)&Wvh, g_Wvh);
    cudaGetSymbolAddress((void**)&Wv8, g_Wv8);
    cudaGetSymbolAddress((void**)&Wvl8, g_Wvl8);
    cudaGetSymbolAddress((void**)&Qh, g_Qh);
    cudaGetSymbolAddress((void**)&Q8, g_Q8);
    cudaGetSymbolAddress((void**)&Ql8, g_Ql8);
    cudaGetSymbolAddress((void**)&Kh, g_Kh);
    cudaGetSymbolAddress((void**)&K8, g_K8);
    cudaGetSymbolAddress((void**)&Kl8, g_Kl8);
    cudaGetSymbolAddress((void**)&Vh, g_Vh);
    cudaGetSymbolAddress((void**)&V8, g_V8);
    cudaGetSymbolAddress((void**)&Vl8, g_Vl8);
    cudaGetSymbolAddress((void**)&Ph, g_Ph);
    cudaGetSymbolAddress((void**)&P8, g_P8);
    cudaGetSymbolAddress((void**)&Pl8, g_Pl8);
    cudaGetSymbolAddress((void**)&Sc, g_S);

    const size_t SD = (size_t)S_ * D_;
    const size_t SS = (size_t)S_ * S_;

    // CSCALE = sAl*sBh = (M'A*2^-12/127)*(M'B/127)
    const float CS_PROJ = (8.0f / 4096.0f / 127.0f) * (0.03125f / 127.0f);
    const float CS_QK   = (4.0f / 4096.0f / 127.0f) * (4.0f / 127.0f);
    const float CS_AV   = (1.0f / 4096.0f / 127.0f) * (4.0f / 127.0f);

    // 1) operand preparation
    wsplit3_kernel<<<dim3(64, 3), 256>>>(Wq, Wk, Wv,
                                         Wqh, Wq8, Wql8,
                                         Wkh, Wk8, Wkl8,
                                         Wvh, Wv8, Wvl8);
    xpose_split_kernel<<<dim3(S_ / 32, D_ / 32, B_), 256>>>(x);

    // 2) projections
    tc_gemm<1024, 0><<<dim3(D_ / 64, S_ / 128, B_), 256, SMEM_SZ>>>(
        xTh, xT8, xTl8, SD, Wqh, Wq8, Wql8, 0, bq, CS_PROJ,
        nullptr, Qh, Q8, Ql8, SD, D_);
    tc_gemm<1024, 0><<<dim3(D_ / 64, S_ / 128, B_), 256, SMEM_SZ>>>(
        xTh, xT8, xTl8, SD, Wkh, Wk8, Wkl8, 0, bk, CS_PROJ,
        nullptr, Kh, K8, Kl8, SD, D_);
    tc_gemm<1024, 1><<<dim3(S_ / 64, D_ / 128, B_), 256, SMEM_SZ>>>(
        Wvh, Wv8, Wvl8, 0, xTh, xT8, xTl8, SD, bv, CS_PROJ,
        nullptr, Vh, V8, Vl8, SD, S_);

    // 3) scores
    tc_gemm<1024, 2><<<dim3(S_ / 64, S_ / 128, B_), 256, SMEM_SZ>>>(
        Qh, Q8, Ql8, SD, Kh, K8, Kl8, SD, nullptr, CS_QK,
        Sc, nullptr, nullptr, nullptr, SS, S_);

    // 4) softmax
    softmax_split_kernel<<<B_ * S_, 256>>>();

    // 5) out = P.V
    tc_gemm<2048, 3><<<dim3(D_ / 64, S_ / 128, B_), 256, SMEM_SZ>>>(
        Ph, P8, Pl8, SS, Vh, V8, Vl8, SD, nullptr, CS_AV,
        out, nullptr, nullptr, nullptr, SD, D_);
}

// round 14
// speedup vs baseline: 1.0002x; 1.0002x over previous
#include <cuda_runtime.h>
#include <cuda_fp16.h>
#include <cstdint>

#define B_ 4
#define D_ 1024
#define S_ 2048

// ---------------------------------------------------------------------------
// Scratch. Each tensor X: Xh = fp16(X), X8 = s8(X/sh), Xl8 = s8((X-Xh)/sl)
// with sh = M'/127, sl = M'*2^-12/127, M' = per-tensor power-of-2 bound.
// ---------------------------------------------------------------------------
__device__ __half   g_xTh[(size_t)B_ * S_ * D_];
__device__ int8_t   g_xT8 [(size_t)B_ * S_ * D_];
__device__ int8_t   g_xTl8[(size_t)B_ * S_ * D_];
__device__ __half   g_Wqh[(size_t)D_ * D_];
__device__ int8_t   g_Wq8[(size_t)D_ * D_], g_Wql8[(size_t)D_ * D_];
__device__ __half   g_Wkh[(size_t)D_ * D_];
__device__ int8_t   g_Wk8[(size_t)D_ * D_], g_Wkl8[(size_t)D_ * D_];
__device__ __half   g_Wvh[(size_t)D_ * D_];
__device__ int8_t   g_Wv8[(size_t)D_ * D_], g_Wvl8[(size_t)D_ * D_];
__device__ __half   g_Qh[(size_t)B_ * S_ * D_];
__device__ int8_t   g_Q8[(size_t)B_ * S_ * D_], g_Ql8[(size_t)B_ * S_ * D_];
__device__ __half   g_Kh[(size_t)B_ * S_ * D_];
__device__ int8_t   g_K8[(size_t)B_ * S_ * D_], g_Kl8[(size_t)B_ * S_ * D_];
__device__ __half   g_Vh[(size_t)B_ * D_ * S_];
__device__ int8_t   g_V8[(size_t)B_ * D_ * S_], g_Vl8[(size_t)B_ * D_ * S_];
__device__ float    g_S [(size_t)B_ * S_ * S_];
__device__ __half   g_Ph[(size_t)B_ * S_ * S_];
__device__ int8_t   g_P8[(size_t)B_ * S_ * S_], g_Pl8[(size_t)B_ * S_ * S_];

// ---------------------------------------------------------------------------
// PTX helpers
// ---------------------------------------------------------------------------
__device__ __forceinline__ uint32_t smem_to_u32(const void* p) {
    uint32_t a;
    asm("{ .reg .u64 t; cvta.to.shared.u64 t, %1; cvt.u32.u64 %0, t; }"
        : "=r"(a) : "l"(p));
    return a;
}

#define CP_ASYNC16(dst_u32, src_ptr) \
    asm volatile("cp.async.cg.shared.global [%0], [%1], 16;" \
                 :: "r"(dst_u32), "l"(src_ptr) : "memory")

#define CP_COMMIT() asm volatile("cp.async.commit_group;" ::: "memory")

#define CP_WAIT(N) asm volatile("cp.async.wait_group %0;" :: "n"(N) : "memory")

#define LDSM4(R, addr) \
    asm volatile("ldmatrix.sync.aligned.m8n8.x4.shared.b16 {%0,%1,%2,%3}, [%4];" \
                 : "=r"((R)[0]), "=r"((R)[1]), "=r"((R)[2]), "=r"((R)[3]) \
                 : "r"(addr))

#define MMA16816(D, A, Bf) \
    asm("mma.sync.aligned.m16n8k16.row.col.f32.f16.f16.f32 " \
        "{%0,%1,%2,%3}, {%4,%5,%6,%7}, {%8,%9}, {%0,%1,%2,%3};" \
        : "+f"((D)[0]), "+f"((D)[1]), "+f"((D)[2]), "+f"((D)[3]) \
        : "r"((A)[0]), "r"((A)[1]), "r"((A)[2]), "r"((A)[3]), \
          "r"((Bf)[0]), "r"((Bf)[1]))

#define MMAI8(D, A, Bf) \
    asm("mma.sync.aligned.m16n8k32.row.col.s32.s8.s8.s32 " \
        "{%0,%1,%2,%3}, {%4,%5,%6,%7}, {%8,%9}, {%0,%1,%2,%3};" \
        : "+r"((D)[0]), "+r"((D)[1]), "+r"((D)[2]), "+r"((D)[3]) \
        : "r"((A)[0]), "r"((A)[1]), "r"((A)[2]), "r"((A)[3]), \
          "r"((Bf)[0]), "r"((Bf)[1]))

__device__ __forceinline__ int8_t q8(float v, float s_inv) {
    int i = __float2int_rn(v * s_inv);
    i = max(-127, min(127, i));
    return (int8_t)i;
}

// 3-form split: fp16 hi; s8 of value (scale inv hi_inv); s8 of residual
// (scale inv lo_inv = hi_inv * 4096).
__device__ __forceinline__ void split3i(float v, float hi_inv, float lo_inv,
                                        __half& h, int8_t& f8, int8_t& fl8) {
    h = __float2half_rn(v);
    f8 = q8(v, hi_inv);
    fl8 = q8(v - __half2float(h), lo_inv);
}

// ---------------------------------------------------------------------------
// GEMM: D[m,n] = sum_k A[m,k]*B[n,k]
//   acc_hi += Ah(fp16)*Bh(fp16)            [2x m16n8k16]
//   acc_lo += A8l*B8 + A8*B8l  (s8, s32)   [2x m16n8k32, ONE accumulator]
//   v = acc_hi + (float)acc_lo * CSCALE    (CSCALE = sAl*sBh = sAh*sBl)
// MODE 0: 3-form out +bias[n]; MODE 1: 3-form out +bias[m];
// MODE 2: fp32 out * 1/32; MODE 3: fp32 out
// CTA 128x64, 8 warps (4m x 2n), warp tile 32x32. 3-stage cp.async.
// fp16 pitch 80B; int8 pitch 48B. Layout identical to round-11 (proven).
// ---------------------------------------------------------------------------
#define SM_AH  0
#define SM_BH  10240
#define SM_A8  15360
#define SM_AL8 21504
#define SM_B8  27648
#define SM_BL8 30720
#define STAGE_BYTES 33792
#define NSTAGE 3

template <int KEL, int MODE>
__global__ __launch_bounds__(256, 2) void tc_gemm(
    const __half* __restrict__ Ah, const int8_t* __restrict__ A8,
    const int8_t* __restrict__ Al8, size_t sA,
    const __half* __restrict__ Bh, const int8_t* __restrict__ B8,
    const int8_t* __restrict__ Bl8, size_t sB,
    const float* __restrict__ bias, float cscale,
    float* __restrict__ outF,
    __half* __restrict__ outH, int8_t* __restrict__ out8,
    int8_t* __restrict__ outL8,
    size_t sO, int ldo)
{
    extern __shared__ char smem[];
    const uint32_t smem_base = smem_to_u32(smem);
    const int tid = threadIdx.x;
    const int wid = tid >> 5;
    const int lid = tid & 31;
    const int wm = wid >> 1;
    const int wn = wid & 1;
    const int b = blockIdx.z;
    const int m0 = blockIdx.y * 128;
    const int n0 = blockIdx.x * 64;

    Ah += (size_t)b * sA; A8 += (size_t)b * sA; Al8 += (size_t)b * sA;
    Bh += (size_t)b * sB; B8 += (size_t)b * sB; Bl8 += (size_t)b * sB;

    float acc_hi[2][4][4];
    int   acc_lo[2][4][4];
    #pragma unroll
    for (int i = 0; i < 2; ++i)
        #pragma unroll
        for (int j = 0; j < 4; ++j)
            #pragma unroll
            for (int k = 0; k < 4; ++k) { acc_hi[i][j][k] = 0.f; acc_lo[i][j][k] = 0; }

    constexpr int NC = KEL / 32;

    auto load_chunk = [&](int c) {
        const int koff = c * 32;
        const uint32_t sb = smem_base + (uint32_t)(c % NSTAGE) * STAGE_BYTES;
        #pragma unroll
        for (int i = 0; i < 2; ++i) {               // fp16 Ah
            const int idx = tid + i * 256;
            const int row = idx >> 2, c16 = idx & 3;
            CP_ASYNC16(sb + SM_AH + row * 80 + c16 * 16,
                       Ah + (size_t)(m0 + row) * KEL + koff + c16 * 8);
        }
        {                                           // fp16 Bh
            const int row = tid >> 2, c16 = tid & 3;
            CP_ASYNC16(sb + SM_BH + row * 80 + c16 * 16,
                       Bh + (size_t)(n0 + row) * KEL + koff + c16 * 8);
        }
        {                                           // s8 A8 + Al8
            const int row = tid >> 1, c16 = tid & 1;
            const size_t ga = (size_t)(m0 + row) * KEL + koff + c16 * 16;
            CP_ASYNC16(sb + SM_A8 + row * 48 + c16 * 16, A8 + ga);
            CP_ASYNC16(sb + SM_AL8 + row * 48 + c16 * 16, Al8 + ga);
        }
        {                                           // s8 B8 / Bl8
            const int t = tid & 127;
            const int row = t >> 1, c16 = t & 1;
            const size_t gb = (size_t)(n0 + row) * KEL + koff + c16 * 16;
            if (tid < 128)
                CP_ASYNC16(sb + SM_B8 + row * 48 + c16 * 16, B8 + gb);
            else
                CP_ASYNC16(sb + SM_BL8 + row * 48 + c16 * 16, Bl8 + gb);
        }
        CP_COMMIT();
    };

    load_chunk(0);
    load_chunk(1);

    const int rowA = wm * 32 + (lid & 15);
    const int rowB = wn * 32 + (lid & 15);
    const uint32_t kb = (uint32_t)((lid >> 4) * 16);

    const int g = lid >> 3;
    const uint32_t a8_lane = (uint32_t)((((g & 1) * 8) + (lid & 7)) * 48 + (g >> 1) * 16);
    const uint32_t b8_lane = (uint32_t)((((g >> 1) * 8) + (lid & 7)) * 48 + (g & 1) * 16);

    #pragma unroll 1
    for (int c = 0; c < NC; ++c) {
        if (c + 1 < NC) { CP_WAIT(1); } else { CP_WAIT(0); }
        __syncthreads();
        if (c + 2 < NC) load_chunk(c + 2);

        const uint32_t sb = smem_base + (uint32_t)(c % NSTAGE) * STAGE_BYTES;

        // ---- fp16 hi phase ----
        #pragma unroll
        for (int ks = 0; ks < 2; ++ks) {
            const uint32_t kbyte = (uint32_t)(ks * 32) + kb;
            uint32_t ah[2][4];
            #pragma unroll
            for (int mt = 0; mt < 2; ++mt)
                LDSM4(ah[mt], sb + SM_AH + (uint32_t)((rowA + mt * 16) * 80) + kbyte);
            uint32_t bh[4][2];
            #pragma unroll
            for (int np = 0; np < 2; ++np) {
                uint32_t t4[4];
                LDSM4(t4, sb + SM_BH + (uint32_t)((rowB + np * 16) * 80) + kbyte);
                bh[2 * np][0] = t4[0]; bh[2 * np][1] = t4[2];
                bh[2 * np + 1][0] = t4[1]; bh[2 * np + 1][1] = t4[3];
            }
            #pragma unroll
            for (int mt = 0; mt < 2; ++mt)
                #pragma unroll
                for (int nt = 0; nt < 4; ++nt)
                    MMA16816(acc_hi[mt][nt], ah[mt], bh[nt]);
        }

        // ---- int8 correction phase: acc_lo += A8l*B8 + A8*B8l ----
        {
            uint32_t a8h[2][4], a8l[2][4];
            #pragma unroll
            for (int mt = 0; mt < 2; ++mt) {
                const uint32_t base = (uint32_t)((wm * 32 + mt * 16) * 48) + a8_lane;
                LDSM4(a8h[mt], sb + SM_A8 + base);
                LDSM4(a8l[mt], sb + SM_AL8 + base);
            }
            uint32_t b8h[4][2], b8l[4][2];
            #pragma unroll
            for (int np = 0; np < 2; ++np) {
                const uint32_t base = (uint32_t)((wn * 32 + np * 16) * 48) + b8_lane;
                uint32_t t4[4];
                LDSM4(t4, sb + SM_B8 + base);
                b8h[2 * np][0] = t4[0]; b8h[2 * np][1] = t4[1];
                b8h[2 * np + 1][0] = t4[2]; b8h[2 * np + 1][1] = t4[3];
                LDSM4(t4, sb + SM_BL8 + base);
                b8l[2 * np][0] = t4[0]; b8l[2 * np][1] = t4[1];
                b8l[2 * np + 1][0] = t4[2]; b8l[2 * np + 1][1] = t4[3];
            }
            #pragma unroll
            for (int mt = 0; mt < 2; ++mt)
                #pragma unroll
                for (int nt = 0; nt < 4; ++nt)
                    MMAI8(acc_lo[mt][nt], a8l[mt], b8h[nt]);
            #pragma unroll
            for (int mt = 0; mt < 2; ++mt)
                #pragma unroll
                for (int nt = 0; nt < 4; ++nt)
                    MMAI8(acc_lo[mt][nt], a8h[mt], b8l[nt]);
        }
    }

    // ---- epilogue ----
    const int gq = lid >> 2, t4i = lid & 3;
    // Q/K/V outputs use M'=4: hi_inv = 127/4, lo_inv = 127*4096/4
    const float OH_INV = 31.75f, OL_INV = 130048.0f;
    #pragma unroll
    for (int mt = 0; mt < 2; ++mt) {
        const int m = m0 + wm * 32 + mt * 16 + gq;
        float bm0 = 0.f, bm8 = 0.f;
        if (MODE == 1) { bm0 = bias[m]; bm8 = bias[m + 8]; }
        #pragma unroll
        for (int nt = 0; nt < 4; ++nt) {
            const int n = n0 + wn * 32 + nt * 8 + 2 * t4i;
            float v0 = acc_hi[mt][nt][0] + (float)acc_lo[mt][nt][0] * cscale;
            float v1 = acc_hi[mt][nt][1] + (float)acc_lo[mt][nt][1] * cscale;
            float v2 = acc_hi[mt][nt][2] + (float)acc_lo[mt][nt][2] * cscale;
            float v3 = acc_hi[mt][nt][3] + (float)acc_lo[mt][nt][3] * cscale;
            if (MODE == 0) {
                const float bn0 = bias[n], bn1 = bias[n + 1];
                v0 += bn0; v1 += bn1; v2 += bn0; v3 += bn1;
            } else if (MODE == 1) {
                v0 += bm0; v1 += bm0; v2 += bm8; v3 += bm8;
            } else if (MODE == 2) {
                v0 *= 0.03125f; v1 *= 0.03125f; v2 *= 0.03125f; v3 *= 0.03125f;
            }
            if (MODE == 0 || MODE == 1) {
                __half h0, h1; int8_t f0, f1, l0, l1;
                const size_t o0 = (size_t)b * sO + (size_t)m * ldo + n;
                split3i(v0, OH_INV, OL_INV, h0, f0, l0);
                split3i(v1, OH_INV, OL_INV, h1, f1, l1);
                { __half2 hh; hh.x = h0; hh.y = h1;
                  *(__half2*)(outH + o0) = hh;
                  char2 u8; u8.x = f0; u8.y = f1; *(char2*)(out8 + o0) = u8;
                  char2 ul; ul.x = l0; ul.y = l1; *(char2*)(outL8 + o0) = ul; }
                const size_t o8 = (size_t)b * sO + (size_t)(m + 8) * ldo + n;
                split3i(v2, OH_INV, OL_INV, h0, f0, l0);
                split3i(v3, OH_INV, OL_INV, h1, f1, l1);
                { __half2 hh; hh.x = h0; hh.y = h1;
                  *(__half2*)(outH + o8) = hh;
                  char2 u8; u8.x = f0; u8.y = f1; *(char2*)(out8 + o8) = u8;
                  char2 ul; ul.x = l0; ul.y = l1; *(char2*)(outL8 + o8) = ul; }
            } else {
                float2 f0; f0.x = v0; f0.y = v1;
                float2 f8; f8.x = v2; f8.y = v3;
                *(float2*)(outF + (size_t)b * sO + (size_t)m * ldo + n) = f0;
                *(float2*)(outF + (size_t)b * sO + (size_t)(m + 8) * ldo + n) = f8;
            }
        }
    }
}

// ---------------------------------------------------------------------------
// Weights: M' = 2^-5. hi_inv = 127*32, lo_inv = 127*4096*32
// ---------------------------------------------------------------------------
__global__ __launch_bounds__(256) void wsplit3_kernel(
    const float* __restrict__ w0, const float* __restrict__ w1,
    const float* __restrict__ w2,
    __half* __restrict__ h0, int8_t* __restrict__ f0, int8_t* __restrict__ l0,
    __half* __restrict__ h1, int8_t* __restrict__ f1, int8_t* __restrict__ l1,
    __half* __restrict__ h2, int8_t* __restrict__ f2, int8_t* __restrict__ l2)
{
    const int which = blockIdx.y;
    const float* w = (which == 0) ? w0 : (which == 1) ? w1 : w2;
    __half* h = (which == 0) ? h0 : (which == 1) ? h1 : h2;
    int8_t* f = (which == 0) ? f0 : (which == 1) ? f1 : f2;
    int8_t* l = (which == 0) ? l0 : (which == 1) ? l1 : l2;
    const int n = D_ * D_;
    const float HI = 127.0f * 32.0f, LO = 127.0f * 4096.0f * 32.0f;
    for (int i = blockIdx.x * 256 + threadIdx.x; i < n; i += gridDim.x * 256) {
        __half hi; int8_t v8, vl8;
        split3i(w[i], HI, LO, hi, v8, vl8);
        h[i] = hi; f[i] = v8; l[i] = vl8;
    }
}

// ---------------------------------------------------------------------------
// x transpose+split: M' = 8. hi_inv = 127/8, lo_inv = 127*512
// ---------------------------------------------------------------------------
__global__ __launch_bounds__(256) void xpose_split_kernel(const float* __restrict__ x)
{
    __shared__ float t[32][33];
    const int b = blockIdx.z;
    const int d0 = blockIdx.y * 32;
    const int s0 = blockIdx.x * 32;
    const int tx = threadIdx.x & 31;
    const int ty = threadIdx.x >> 5;
    const float* X = x + (size_t)b * D_ * S_;
    const float HI = 127.0f / 8.0f, LO = 127.0f * 512.0f;

    #pragma unroll
    for (int i = 0; i < 4; ++i)
        t[ty + i * 8][tx] = X[(size_t)(d0 + ty + i * 8) * S_ + s0 + tx];
    __syncthreads();
    #pragma unroll
    for (int i = 0; i < 4; ++i) {
        const int s = s0 + ty + i * 8;
        const int d = d0 + tx;
        const float v = t[tx][ty + i * 8];
        __half hi; int8_t v8, vl8;
        split3i(v, HI, LO, hi, v8, vl8);
        const size_t idx = (size_t)b * S_ * D_ + (size_t)s * D_ + d;
        g_xTh[idx] = hi;
        g_xT8[idx] = v8;
        g_xTl8[idx] = vl8;
    }
}

// ---------------------------------------------------------------------------
// softmax: P in [0,1], M' = 1. hi_inv = 127, lo_inv = 127*4096
// ---------------------------------------------------------------------------
__global__ __launch_bounds__(256) void softmax_split_kernel()
{
    const size_t row = blockIdx.x;
    const float* __restrict__ p = g_S + row * S_;
    __half* __restrict__ ph = g_Ph + row * S_;
    int8_t* __restrict__ p8 = g_P8 + row * S_;
    int8_t* __restrict__ pl8 = g_Pl8 + row * S_;
    const int tid = threadIdx.x;
    const float HI = 127.0f, LO = 127.0f * 4096.0f;

    float v[8];
    #pragma unroll
    for (int i = 0; i < 8; ++i) v[i] = p[i * 256 + tid];

    float m = v[0];
    #pragma unroll
    for (int i = 1; i < 8; ++i) m = fmaxf(m, v[i]);

    __shared__ float red[8];
    #pragma unroll
    for (int o = 16; o > 0; o >>= 1)
        m = fmaxf(m, __shfl_xor_sync(0xffffffffu, m, o));
    if ((tid & 31) == 0) red[tid >> 5] = m;
    __syncthreads();
    m = red[0];
    #pragma unroll
    for (int i = 1; i < 8; ++i) m = fmaxf(m, red[i]);
    __syncthreads();

    float s = 0.f;
    #pragma unroll
    for (int i = 0; i < 8; ++i) { v[i] = expf(v[i] - m); s += v[i]; }
    #pragma unroll
    for (int o = 16; o > 0; o >>= 1)
        s += __shfl_xor_sync(0xffffffffu, s, o);
    if ((tid & 31) == 0) red[tid >> 5] = s;
    __syncthreads();
    s = 0.f;
    #pragma unroll
    for (int i = 0; i < 8; ++i) s += red[i];

    const float inv = 1.0f / s;
    #pragma unroll
    for (int i = 0; i < 8; ++i) {
        __half hi; int8_t v8, vl8;
        split3i(v[i] * inv, HI, LO, hi, v8, vl8);
        ph[i * 256 + tid] = hi;
        p8[i * 256 + tid] = v8;
        pl8[i * 256 + tid] = vl8;
    }
}

// ---------------------------------------------------------------------------
extern "C" void kernel_launch(void* const* d_in, const int* in_sizes, int n_in,
                              void* d_out, int out_size)
{
    const float* x  = (const float*)d_in[0];
    const float* Wq = (const float*)d_in[1];
    const float* bq = (const float*)d_in[2];
    const float* Wk = (const float*)d_in[3];
    const float* bk = (const float*)d_in[4];
    const float* Wv = (const float*)d_in[5];
    const float* bv = (const float*)d_in[6];
    float* out = (float*)d_out;

    const int SMEM_SZ = NSTAGE * STAGE_BYTES;   // 101376

    cudaFuncSetAttribute(tc_gemm<1024, 0>, cudaFuncAttributeMaxDynamicSharedMemorySize, SMEM_SZ);
    cudaFuncSetAttribute(tc_gemm<1024, 1>, cudaFuncAttributeMaxDynamicSharedMemorySize, SMEM_SZ);
    cudaFuncSetAttribute(tc_gemm<1024, 2>, cudaFuncAttributeMaxDynamicSharedMemorySize, SMEM_SZ);
    cudaFuncSetAttribute(tc_gemm<2048, 3>, cudaFuncAttributeMaxDynamicSharedMemorySize, SMEM_SZ);

    __half *xTh, *Wqh, *Wkh, *Wvh, *Qh, *Kh, *Vh, *Ph;
    int8_t *xT8, *xTl8, *Wq8, *Wql8, *Wk8, *Wkl8, *Wv8, *Wvl8;
    int8_t *Q8, *Ql8, *K8, *Kl8, *V8, *Vl8, *P8, *Pl8;
    float* Sc;
    cudaGetSymbolAddress((void**)&xTh, g_xTh);
    cudaGetSymbolAddress((void**)&xT8, g_xT8);
    cudaGetSymbolAddress((void**)&xTl8, g_xTl8);
    cudaGetSymbolAddress((void**)&Wqh, g_Wqh);
    cudaGetSymbolAddress((void**)&Wq8, g_Wq8);
    cudaGetSymbolAddress((void**)&Wql8, g_Wql8);
    cudaGetSymbolAddress((void**)&Wkh, g_Wkh);
    cudaGetSymbolAddress((void**)&Wk8, g_Wk8);
    cudaGetSymbolAddress((void**)&Wkl8, g_Wkl8);
    cudaGetSymbolAddress((void**)&Wvh, g_Wvh);
    cudaGetSymbolAddress((void**)&Wv8, g_Wv8);
    cudaGetSymbolAddress((void**)&Wvl8, g_Wvl8);
    cudaGetSymbolAddress((void**)&Qh, g_Qh);
    cudaGetSymbolAddress((void**)&Q8, g_Q8);
    cudaGetSymbolAddress((void**)&Ql8, g_Ql8);
    cudaGetSymbolAddress((void**)&Kh, g_Kh);
    cudaGetSymbolAddress((void**)&K8, g_K8);
    cudaGetSymbolAddress((void**)&Kl8, g_Kl8);
    cudaGetSymbolAddress((void**)&Vh, g_Vh);
    cudaGetSymbolAddress((void**)&V8, g_V8);
    cudaGetSymbolAddress((void**)&Vl8, g_Vl8);
    cudaGetSymbolAddress((void**)&Ph, g_Ph);
    cudaGetSymbolAddress((void**)&P8, g_P8);
    cudaGetSymbolAddress((void**)&Pl8, g_Pl8);
    cudaGetSymbolAddress((void**)&Sc, g_S);

    const size_t SD = (size_t)S_ * D_;
    const size_t SS = (size_t)S_ * S_;

    // CSCALE = sAl*sBh = (M'A*2^-12/127)*(M'B/127)
    const float CS_PROJ = (8.0f / 4096.0f / 127.0f) * (0.03125f / 127.0f);
    const float CS_QK   = (4.0f / 4096.0f / 127.0f) * (4.0f / 127.0f);
    const float CS_AV   = (1.0f / 4096.0f / 127.0f) * (4.0f / 127.0f);

    // 1) operand preparation
    wsplit3_kernel<<<dim3(64, 3), 256>>>(Wq, Wk, Wv,
                                         Wqh, Wq8, Wql8,
                                         Wkh, Wk8, Wkl8,
                                         Wvh, Wv8, Wvl8);
    xpose_split_kernel<<<dim3(S_ / 32, D_ / 32, B_), 256>>>(x);

    // 2) projections
    tc_gemm<1024, 0><<<dim3(D_ / 64, S_ / 128, B_), 256, SMEM_SZ>>>(
        xTh, xT8, xTl8, SD, Wqh, Wq8, Wql8, 0, bq, CS_PROJ,
        nullptr, Qh, Q8, Ql8, SD, D_);
    tc_gemm<1024, 0><<<dim3(D_ / 64, S_ / 128, B_), 256, SMEM_SZ>>>(
        xTh, xT8, xTl8, SD, Wkh, Wk8, Wkl8, 0, bk, CS_PROJ,
        nullptr, Kh, K8, Kl8, SD, D_);
    tc_gemm<1024, 1><<<dim3(S_ / 64, D_ / 128, B_), 256, SMEM_SZ>>>(
        Wvh, Wv8, Wvl8, 0, xTh, xT8, xTl8, SD, bv, CS_PROJ,
        nullptr, Vh, V8, Vl8, SD, S_);

    // 3) scores
    tc_gemm<1024, 2><<<dim3(S_ / 64, S_ / 128, B_), 256, SMEM_SZ>>>(
        Qh, Q8, Ql8, SD, Kh, K8, Kl8, SD, nullptr, CS_QK,
        Sc, nullptr, nullptr, nullptr, SS, S_);

    // 4) softmax
    softmax_split_kernel<<<B_ * S_, 256>>>();

    // 5) out = P.V
    tc_gemm<2048, 3><<<dim3(D_ / 64, S_ / 128, B_), 256, SMEM_SZ>>>(
        Ph, P8, Pl8, SS, Vh, V8, Vl8, SD, nullptr, CS_AV,
        out, nullptr, nullptr, nullptr, SD, D_);
}

// round 15
// speedup vs baseline: 1.0009x; 1.0007x over previous
#include <cuda_runtime.h>
#include <cuda_fp16.h>
#include <cstdint>

#define B_ 4
#define D_ 1024
#define S_ 2048

// ---------------------------------------------------------------------------
// Scratch. Each tensor X: Xh = fp16(X), X8 = s8(X/sh), Xl8 = s8((X-Xh)/sl)
// with sh = M'/127, sl = M'*2^-12/127, M' = per-tensor power-of-2 bound.
// ---------------------------------------------------------------------------
__device__ __half   g_xTh[(size_t)B_ * S_ * D_];
__device__ int8_t   g_xT8 [(size_t)B_ * S_ * D_];
__device__ int8_t   g_xTl8[(size_t)B_ * S_ * D_];
__device__ __half   g_Wqh[(size_t)D_ * D_];
__device__ int8_t   g_Wq8[(size_t)D_ * D_], g_Wql8[(size_t)D_ * D_];
__device__ __half   g_Wkh[(size_t)D_ * D_];
__device__ int8_t   g_Wk8[(size_t)D_ * D_], g_Wkl8[(size_t)D_ * D_];
__device__ __half   g_Wvh[(size_t)D_ * D_];
__device__ int8_t   g_Wv8[(size_t)D_ * D_], g_Wvl8[(size_t)D_ * D_];
__device__ __half   g_Qh[(size_t)B_ * S_ * D_];
__device__ int8_t   g_Q8[(size_t)B_ * S_ * D_], g_Ql8[(size_t)B_ * S_ * D_];
__device__ __half   g_Kh[(size_t)B_ * S_ * D_];
__device__ int8_t   g_K8[(size_t)B_ * S_ * D_], g_Kl8[(size_t)B_ * S_ * D_];
__device__ __half   g_Vh[(size_t)B_ * D_ * S_];
__device__ int8_t   g_V8[(size_t)B_ * D_ * S_], g_Vl8[(size_t)B_ * D_ * S_];
__device__ float    g_S [(size_t)B_ * S_ * S_];
__device__ __half   g_Ph[(size_t)B_ * S_ * S_];
__device__ int8_t   g_P8[(size_t)B_ * S_ * S_], g_Pl8[(size_t)B_ * S_ * S_];

// ---------------------------------------------------------------------------
// PTX helpers
// ---------------------------------------------------------------------------
__device__ __forceinline__ uint32_t smem_to_u32(const void* p) {
    uint32_t a;
    asm("{ .reg .u64 t; cvta.to.shared.u64 t, %1; cvt.u32.u64 %0, t; }"
        : "=r"(a) : "l"(p));
    return a;
}

#define CP_ASYNC16(dst_u32, src_ptr) \
    asm volatile("cp.async.cg.shared.global [%0], [%1], 16;" \
                 :: "r"(dst_u32), "l"(src_ptr) : "memory")

#define CP_COMMIT() asm volatile("cp.async.commit_group;" ::: "memory")

#define CP_WAIT(N) asm volatile("cp.async.wait_group %0;" :: "n"(N) : "memory")

#define LDSM4(R, addr) \
    asm volatile("ldmatrix.sync.aligned.m8n8.x4.shared.b16 {%0,%1,%2,%3}, [%4];" \
                 : "=r"((R)[0]), "=r"((R)[1]), "=r"((R)[2]), "=r"((R)[3]) \
                 : "r"(addr))

#define MMA16816(D, A, Bf) \
    asm("mma.sync.aligned.m16n8k16.row.col.f32.f16.f16.f32 " \
        "{%0,%1,%2,%3}, {%4,%5,%6,%7}, {%8,%9}, {%0,%1,%2,%3};" \
        : "+f"((D)[0]), "+f"((D)[1]), "+f"((D)[2]), "+f"((D)[3]) \
        : "r"((A)[0]), "r"((A)[1]), "r"((A)[2]), "r"((A)[3]), \
          "r"((Bf)[0]), "r"((Bf)[1]))

#define MMAI8(D, A, Bf) \
    asm("mma.sync.aligned.m16n8k32.row.col.s32.s8.s8.s32 " \
        "{%0,%1,%2,%3}, {%4,%5,%6,%7}, {%8,%9}, {%0,%1,%2,%3};" \
        : "+r"((D)[0]), "+r"((D)[1]), "+r"((D)[2]), "+r"((D)[3]) \
        : "r"((A)[0]), "r"((A)[1]), "r"((A)[2]), "r"((A)[3]), \
          "r"((Bf)[0]), "r"((Bf)[1]))

__device__ __forceinline__ int8_t q8(float v, float s_inv) {
    int i = __float2int_rn(v * s_inv);
    i = max(-127, min(127, i));
    return (int8_t)i;
}

// 3-form split: fp16 hi; s8 of value (scale inv hi_inv); s8 of residual
// (scale inv lo_inv = hi_inv * 4096).
__device__ __forceinline__ void split3i(float v, float hi_inv, float lo_inv,
                                        __half& h, int8_t& f8, int8_t& fl8) {
    h = __float2half_rn(v);
    f8 = q8(v, hi_inv);
    fl8 = q8(v - __half2float(h), lo_inv);
}

// ---------------------------------------------------------------------------
// GEMM: D[m,n] = sum_k A[m,k]*B[n,k]
//   acc_hi += Ah(fp16)*Bh(fp16)            [2x m16n8k16]
//   acc_lo += A8l*B8 + A8*B8l  (s8, s32)   [2x m16n8k32, ONE accumulator]
//   v = acc_hi + (float)acc_lo * CSCALE    (CSCALE = sAl*sBh = sAh*sBl)
// MODE 0: 3-form out +bias[n]; MODE 1: 3-form out +bias[m];
// MODE 2: fp32 out * 1/32; MODE 3: fp32 out
// CTA 128x64, 8 warps (4m x 2n), warp tile 32x32. 3-stage cp.async.
// fp16 pitch 80B; int8 pitch 48B. Layout identical to round-11 (proven).
// ---------------------------------------------------------------------------
#define SM_AH  0
#define SM_BH  10240
#define SM_A8  15360
#define SM_AL8 21504
#define SM_B8  27648
#define SM_BL8 30720
#define STAGE_BYTES 33792
#define NSTAGE 3

template <int KEL, int MODE>
__global__ __launch_bounds__(256, 2) void tc_gemm(
    const __half* __restrict__ Ah, const int8_t* __restrict__ A8,
    const int8_t* __restrict__ Al8, size_t sA,
    const __half* __restrict__ Bh, const int8_t* __restrict__ B8,
    const int8_t* __restrict__ Bl8, size_t sB,
    const float* __restrict__ bias, float cscale,
    float* __restrict__ outF,
    __half* __restrict__ outH, int8_t* __restrict__ out8,
    int8_t* __restrict__ outL8,
    size_t sO, int ldo)
{
    extern __shared__ char smem[];
    const uint32_t smem_base = smem_to_u32(smem);
    const int tid = threadIdx.x;
    const int wid = tid >> 5;
    const int lid = tid & 31;
    const int wm = wid >> 1;
    const int wn = wid & 1;
    const int b = blockIdx.z;
    const int m0 = blockIdx.y * 128;
    const int n0 = blockIdx.x * 64;

    Ah += (size_t)b * sA; A8 += (size_t)b * sA; Al8 += (size_t)b * sA;
    Bh += (size_t)b * sB; B8 += (size_t)b * sB; Bl8 += (size_t)b * sB;

    float acc_hi[2][4][4];
    int   acc_lo[2][4][4];
    #pragma unroll
    for (int i = 0; i < 2; ++i)
        #pragma unroll
        for (int j = 0; j < 4; ++j)
            #pragma unroll
            for (int k = 0; k < 4; ++k) { acc_hi[i][j][k] = 0.f; acc_lo[i][j][k] = 0; }

    constexpr int NC = KEL / 32;

    auto load_chunk = [&](int c) {
        const int koff = c * 32;
        const uint32_t sb = smem_base + (uint32_t)(c % NSTAGE) * STAGE_BYTES;
        #pragma unroll
        for (int i = 0; i < 2; ++i) {               // fp16 Ah
            const int idx = tid + i * 256;
            const int row = idx >> 2, c16 = idx & 3;
            CP_ASYNC16(sb + SM_AH + row * 80 + c16 * 16,
                       Ah + (size_t)(m0 + row) * KEL + koff + c16 * 8);
        }
        {                                           // fp16 Bh
            const int row = tid >> 2, c16 = tid & 3;
            CP_ASYNC16(sb + SM_BH + row * 80 + c16 * 16,
                       Bh + (size_t)(n0 + row) * KEL + koff + c16 * 8);
        }
        {                                           // s8 A8 + Al8
            const int row = tid >> 1, c16 = tid & 1;
            const size_t ga = (size_t)(m0 + row) * KEL + koff + c16 * 16;
            CP_ASYNC16(sb + SM_A8 + row * 48 + c16 * 16, A8 + ga);
            CP_ASYNC16(sb + SM_AL8 + row * 48 + c16 * 16, Al8 + ga);
        }
        {                                           // s8 B8 / Bl8
            const int t = tid & 127;
            const int row = t >> 1, c16 = t & 1;
            const size_t gb = (size_t)(n0 + row) * KEL + koff + c16 * 16;
            if (tid < 128)
                CP_ASYNC16(sb + SM_B8 + row * 48 + c16 * 16, B8 + gb);
            else
                CP_ASYNC16(sb + SM_BL8 + row * 48 + c16 * 16, Bl8 + gb);
        }
        CP_COMMIT();
    };

    load_chunk(0);
    load_chunk(1);

    const int rowA = wm * 32 + (lid & 15);
    const int rowB = wn * 32 + (lid & 15);
    const uint32_t kb = (uint32_t)((lid >> 4) * 16);

    const int g = lid >> 3;
    const uint32_t a8_lane = (uint32_t)((((g & 1) * 8) + (lid & 7)) * 48 + (g >> 1) * 16);
    const uint32_t b8_lane = (uint32_t)((((g >> 1) * 8) + (lid & 7)) * 48 + (g & 1) * 16);

    #pragma unroll 1
    for (int c = 0; c < NC; ++c) {
        if (c + 1 < NC) { CP_WAIT(1); } else { CP_WAIT(0); }
        __syncthreads();
        if (c + 2 < NC) load_chunk(c + 2);

        const uint32_t sb = smem_base + (uint32_t)(c % NSTAGE) * STAGE_BYTES;

        // ---- fp16 hi phase ----
        #pragma unroll
        for (int ks = 0; ks < 2; ++ks) {
            const uint32_t kbyte = (uint32_t)(ks * 32) + kb;
            uint32_t ah[2][4];
            #pragma unroll
            for (int mt = 0; mt < 2; ++mt)
                LDSM4(ah[mt], sb + SM_AH + (uint32_t)((rowA + mt * 16) * 80) + kbyte);
            uint32_t bh[4][2];
            #pragma unroll
            for (int np = 0; np < 2; ++np) {
                uint32_t t4[4];
                LDSM4(t4, sb + SM_BH + (uint32_t)((rowB + np * 16) * 80) + kbyte);
                bh[2 * np][0] = t4[0]; bh[2 * np][1] = t4[2];
                bh[2 * np + 1][0] = t4[1]; bh[2 * np + 1][1] = t4[3];
            }
            #pragma unroll
            for (int mt = 0; mt < 2; ++mt)
                #pragma unroll
                for (int nt = 0; nt < 4; ++nt)
                    MMA16816(acc_hi[mt][nt], ah[mt], bh[nt]);
        }

        // ---- int8 correction phase: acc_lo += A8l*B8 + A8*B8l ----
        {
            uint32_t a8h[2][4], a8l[2][4];
            #pragma unroll
            for (int mt = 0; mt < 2; ++mt) {
                const uint32_t base = (uint32_t)((wm * 32 + mt * 16) * 48) + a8_lane;
                LDSM4(a8h[mt], sb + SM_A8 + base);
                LDSM4(a8l[mt], sb + SM_AL8 + base);
            }
            uint32_t b8h[4][2], b8l[4][2];
            #pragma unroll
            for (int np = 0; np < 2; ++np) {
                const uint32_t base = (uint32_t)((wn * 32 + np * 16) * 48) + b8_lane;
                uint32_t t4[4];
                LDSM4(t4, sb + SM_B8 + base);
                b8h[2 * np][0] = t4[0]; b8h[2 * np][1] = t4[1];
                b8h[2 * np + 1][0] = t4[2]; b8h[2 * np + 1][1] = t4[3];
                LDSM4(t4, sb + SM_BL8 + base);
                b8l[2 * np][0] = t4[0]; b8l[2 * np][1] = t4[1];
                b8l[2 * np + 1][0] = t4[2]; b8l[2 * np + 1][1] = t4[3];
            }
            #pragma unroll
            for (int mt = 0; mt < 2; ++mt)
                #pragma unroll
                for (int nt = 0; nt < 4; ++nt)
                    MMAI8(acc_lo[mt][nt], a8l[mt], b8h[nt]);
            #pragma unroll
            for (int mt = 0; mt < 2; ++mt)
                #pragma unroll
                for (int nt = 0; nt < 4; ++nt)
                    MMAI8(acc_lo[mt][nt], a8h[mt], b8l[nt]);
        }
    }

    // ---- epilogue ----
    const int gq = lid >> 2, t4i = lid & 3;
    // Q/K/V outputs use M'=4: hi_inv = 127/4, lo_inv = 127*4096/4
    const float OH_INV = 31.75f, OL_INV = 130048.0f;
    #pragma unroll
    for (int mt = 0; mt < 2; ++mt) {
        const int m = m0 + wm * 32 + mt * 16 + gq;
        float bm0 = 0.f, bm8 = 0.f;
        if (MODE == 1) { bm0 = bias[m]; bm8 = bias[m + 8]; }
        #pragma unroll
        for (int nt = 0; nt < 4; ++nt) {
            const int n = n0 + wn * 32 + nt * 8 + 2 * t4i;
            float v0 = acc_hi[mt][nt][0] + (float)acc_lo[mt][nt][0] * cscale;
            float v1 = acc_hi[mt][nt][1] + (float)acc_lo[mt][nt][1] * cscale;
            float v2 = acc_hi[mt][nt][2] + (float)acc_lo[mt][nt][2] * cscale;
            float v3 = acc_hi[mt][nt][3] + (float)acc_lo[mt][nt][3] * cscale;
            if (MODE == 0) {
                const float bn0 = bias[n], bn1 = bias[n + 1];
                v0 += bn0; v1 += bn1; v2 += bn0; v3 += bn1;
            } else if (MODE == 1) {
                v0 += bm0; v1 += bm0; v2 += bm8; v3 += bm8;
            } else if (MODE == 2) {
                v0 *= 0.03125f; v1 *= 0.03125f; v2 *= 0.03125f; v3 *= 0.03125f;
            }
            if (MODE == 0 || MODE == 1) {
                __half h0, h1; int8_t f0, f1, l0, l1;
                const size_t o0 = (size_t)b * sO + (size_t)m * ldo + n;
                split3i(v0, OH_INV, OL_INV, h0, f0, l0);
                split3i(v1, OH_INV, OL_INV, h1, f1, l1);
                { __half2 hh; hh.x = h0; hh.y = h1;
                  *(__half2*)(outH + o0) = hh;
                  char2 u8; u8.x = f0; u8.y = f1; *(char2*)(out8 + o0) = u8;
                  char2 ul; ul.x = l0; ul.y = l1; *(char2*)(outL8 + o0) = ul; }
                const size_t o8 = (size_t)b * sO + (size_t)(m + 8) * ldo + n;
                split3i(v2, OH_INV, OL_INV, h0, f0, l0);
                split3i(v3, OH_INV, OL_INV, h1, f1, l1);
                { __half2 hh; hh.x = h0; hh.y = h1;
                  *(__half2*)(outH + o8) = hh;
                  char2 u8; u8.x = f0; u8.y = f1; *(char2*)(out8 + o8) = u8;
                  char2 ul; ul.x = l0; ul.y = l1; *(char2*)(outL8 + o8) = ul; }
            } else {
                float2 f0; f0.x = v0; f0.y = v1;
                float2 f8; f8.x = v2; f8.y = v3;
                *(float2*)(outF + (size_t)b * sO + (size_t)m * ldo + n) = f0;
                *(float2*)(outF + (size_t)b * sO + (size_t)(m + 8) * ldo + n) = f8;
            }
        }
    }
}

// ---------------------------------------------------------------------------
// Weights: M' = 2^-5. hi_inv = 127*32, lo_inv = 127*4096*32
// ---------------------------------------------------------------------------
__global__ __launch_bounds__(256) void wsplit3_kernel(
    const float* __restrict__ w0, const float* __restrict__ w1,
    const float* __restrict__ w2,
    __half* __restrict__ h0, int8_t* __restrict__ f0, int8_t* __restrict__ l0,
    __half* __restrict__ h1, int8_t* __restrict__ f1, int8_t* __restrict__ l1,
    __half* __restrict__ h2, int8_t* __restrict__ f2, int8_t* __restrict__ l2)
{
    const int which = blockIdx.y;
    const float* w = (which == 0) ? w0 : (which == 1) ? w1 : w2;
    __half* h = (which == 0) ? h0 : (which == 1) ? h1 : h2;
    int8_t* f = (which == 0) ? f0 : (which == 1) ? f1 : f2;
    int8_t* l = (which == 0) ? l0 : (which == 1) ? l1 : l2;
    const int n = D_ * D_;
    const float HI = 127.0f * 32.0f, LO = 127.0f * 4096.0f * 32.0f;
    for (int i = blockIdx.x * 256 + threadIdx.x; i < n; i += gridDim.x * 256) {
        __half hi; int8_t v8, vl8;
        split3i(w[i], HI, LO, hi, v8, vl8);
        h[i] = hi; f[i] = v8; l[i] = vl8;
    }
}

// ---------------------------------------------------------------------------
// x transpose+split: M' = 8. hi_inv = 127/8, lo_inv = 127*512
// ---------------------------------------------------------------------------
__global__ __launch_bounds__(256) void xpose_split_kernel(const float* __restrict__ x)
{
    __shared__ float t[32][33];
    const int b = blockIdx.z;
    const int d0 = blockIdx.y * 32;
    const int s0 = blockIdx.x * 32;
    const int tx = threadIdx.x & 31;
    const int ty = threadIdx.x >> 5;
    const float* X = x + (size_t)b * D_ * S_;
    const float HI = 127.0f / 8.0f, LO = 127.0f * 512.0f;

    #pragma unroll
    for (int i = 0; i < 4; ++i)
        t[ty + i * 8][tx] = X[(size_t)(d0 + ty + i * 8) * S_ + s0 + tx];
    __syncthreads();
    #pragma unroll
    for (int i = 0; i < 4; ++i) {
        const int s = s0 + ty + i * 8;
        const int d = d0 + tx;
        const float v = t[tx][ty + i * 8];
        __half hi; int8_t v8, vl8;
        split3i(v, HI, LO, hi, v8, vl8);
        const size_t idx = (size_t)b * S_ * D_ + (size_t)s * D_ + d;
        g_xTh[idx] = hi;
        g_xT8[idx] = v8;
        g_xTl8[idx] = vl8;
    }
}

// ---------------------------------------------------------------------------
// softmax: P in [0,1], M' = 1. hi_inv = 127, lo_inv = 127*4096
// ---------------------------------------------------------------------------
__global__ __launch_bounds__(256) void softmax_split_kernel()
{
    const size_t row = blockIdx.x;
    const float* __restrict__ p = g_S + row * S_;
    __half* __restrict__ ph = g_Ph + row * S_;
    int8_t* __restrict__ p8 = g_P8 + row * S_;
    int8_t* __restrict__ pl8 = g_Pl8 + row * S_;
    const int tid = threadIdx.x;
    const float HI = 127.0f, LO = 127.0f * 4096.0f;

    float v[8];
    #pragma unroll
    for (int i = 0; i < 8; ++i) v[i] = p[i * 256 + tid];

    float m = v[0];
    #pragma unroll
    for (int i = 1; i < 8; ++i) m = fmaxf(m, v[i]);

    __shared__ float red[8];
    #pragma unroll
    for (int o = 16; o > 0; o >>= 1)
        m = fmaxf(m, __shfl_xor_sync(0xffffffffu, m, o));
    if ((tid & 31) == 0) red[tid >> 5] = m;
    __syncthreads();
    m = red[0];
    #pragma unroll
    for (int i = 1; i < 8; ++i) m = fmaxf(m, red[i]);
    __syncthreads();

    float s = 0.f;
    #pragma unroll
    for (int i = 0; i < 8; ++i) { v[i] = expf(v[i] - m); s += v[i]; }
    #pragma unroll
    for (int o = 16; o > 0; o >>= 1)
        s += __shfl_xor_sync(0xffffffffu, s, o);
    if ((tid & 31) == 0) red[tid >> 5] = s;
    __syncthreads();
    s = 0.f;
    #pragma unroll
    for (int i = 0; i < 8; ++i) s += red[i];

    const float inv = 1.0f / s;
    #pragma unroll
    for (int i = 0; i < 8; ++i) {
        __half hi; int8_t v8, vl8;
        split3i(v[i] * inv, HI, LO, hi, v8, vl8);
        ph[i * 256 + tid] = hi;
        p8[i * 256 + tid] = v8;
        pl8[i * 256 + tid] = vl8;
    }
}

// ---------------------------------------------------------------------------
extern "C" void kernel_launch(void* const* d_in, const int* in_sizes, int n_in,
                              void* d_out, int out_size)
{
    const float* x  = (const float*)d_in[0];
    const float* Wq = (const float*)d_in[1];
    const float* bq = (const float*)d_in[2];
    const float* Wk = (const float*)d_in[3];
    const float* bk = (const float*)d_in[4];
    const float* Wv = (const float*)d_in[5];
    const float* bv = (const float*)d_in[6];
    float* out = (float*)d_out;

    const int SMEM_SZ = NSTAGE * STAGE_BYTES;   // 101376

    cudaFuncSetAttribute(tc_gemm<1024, 0>, cudaFuncAttributeMaxDynamicSharedMemorySize, SMEM_SZ);
    cudaFuncSetAttribute(tc_gemm<1024, 1>, cudaFuncAttributeMaxDynamicSharedMemorySize, SMEM_SZ);
    cudaFuncSetAttribute(tc_gemm<1024, 2>, cudaFuncAttributeMaxDynamicSharedMemorySize, SMEM_SZ);
    cudaFuncSetAttribute(tc_gemm<2048, 3>, cudaFuncAttributeMaxDynamicSharedMemorySize, SMEM_SZ);

    __half *xTh, *Wqh, *Wkh, *Wvh, *Qh, *Kh, *Vh, *Ph;
    int8_t *xT8, *xTl8, *Wq8, *Wql8, *Wk8, *Wkl8, *Wv8, *Wvl8;
    int8_t *Q8, *Ql8, *K8, *Kl8, *V8, *Vl8, *P8, *Pl8;
    float* Sc;
    cudaGetSymbolAddress((void**)&xTh, g_xTh);
    cudaGetSymbolAddress((void**)&xT8, g_xT8);
    cudaGetSymbolAddress((void**)&xTl8, g_xTl8);
    cudaGetSymbolAddress((void**)&Wqh, g_Wqh);
    cudaGetSymbolAddress((void**)&Wq8, g_Wq8);
    cudaGetSymbolAddress((void**)&Wql8, g_Wql8);
    cudaGetSymbolAddress((void**)&Wkh, g_Wkh);
    cudaGetSymbolAddress((void**)&Wk8, g_Wk8);
    cudaGetSymbolAddress((void**)&Wkl8, g_Wkl8);
    cudaGetSymbolAddress((void**)&Wvh, g_Wvh);
    cudaGetSymbolAddress((void**)&Wv8, g_Wv8);
    cudaGetSymbolAddress((void**)&Wvl8, g_Wvl8);
    cudaGetSymbolAddress((void**)&Qh, g_Qh);
    cudaGetSymbolAddress((void**)&Q8, g_Q8);
    cudaGetSymbolAddress((void**)&Ql8, g_Ql8);
    cudaGetSymbolAddress((void**)&Kh, g_Kh);
    cudaGetSymbolAddress((void**)&K8, g_K8);
    cudaGetSymbolAddress((void**)&Kl8, g_Kl8);
    cudaGetSymbolAddress((void**)&Vh, g_Vh);
    cudaGetSymbolAddress((void**)&V8, g_V8);
    cudaGetSymbolAddress((void**)&Vl8, g_Vl8);
    cudaGetSymbolAddress((void**)&Ph, g_Ph);
    cudaGetSymbolAddress((void**)&P8, g_P8);
    cudaGetSymbolAddress((void**)&Pl8, g_Pl8);
    cudaGetSymbolAddress((void**)&Sc, g_S);

    const size_t SD = (size_t)S_ * D_;
    const size_t SS = (size_t)S_ * S_;

    // CSCALE = sAl*sBh = (M'A*2^-12/127)*(M'B/127)
    const float CS_PROJ = (8.0f / 4096.0f / 127.0f) * (0.03125f / 127.0f);
    const float CS_QK   = (4.0f / 4096.0f / 127.0f) * (4.0f / 127.0f);
    const float CS_AV   = (1.0f / 4096.0f / 127.0f) * (4.0f / 127.0f);

    // 1) operand preparation
    wsplit3_kernel<<<dim3(64, 3), 256>>>(Wq, Wk, Wv,
                                         Wqh, Wq8, Wql8,
                                         Wkh, Wk8, Wkl8,
                                         Wvh, Wv8, Wvl8);
    xpose_split_kernel<<<dim3(S_ / 32, D_ / 32, B_), 256>>>(x);

    // 2) projections
    tc_gemm<1024, 0><<<dim3(D_ / 64, S_ / 128, B_), 256, SMEM_SZ>>>(
        xTh, xT8, xTl8, SD, Wqh, Wq8, Wql8, 0, bq, CS_PROJ,
        nullptr, Qh, Q8, Ql8, SD, D_);
    tc_gemm<1024, 0><<<dim3(D_ / 64, S_ / 128, B_), 256, SMEM_SZ>>>(
        xTh, xT8, xTl8, SD, Wkh, Wk8, Wkl8, 0, bk, CS_PROJ,
        nullptr, Kh, K8, Kl8, SD, D_);
    tc_gemm<1024, 1><<<dim3(S_ / 64, D_ / 128, B_), 256, SMEM_SZ>>>(
        Wvh, Wv8, Wvl8, 0, xTh, xT8, xTl8, SD, bv, CS_PROJ,
        nullptr, Vh, V8, Vl8, SD, S_);

    // 3) scores
    tc_gemm<1024, 2><<<dim3(S_ / 64, S_ / 128, B_), 256, SMEM_SZ>>>(
        Qh, Q8, Ql8, SD, Kh, K8, Kl8, SD, nullptr, CS_QK,
        Sc, nullptr, nullptr, nullptr, SS, S_);

    // 4) softmax
    softmax_split_kernel<<<B_ * S_, 256>>>();

    // 5) out = P.V
    tc_gemm<2048, 3><<<dim3(D_ / 64, S_ / 128, B_), 256, SMEM_SZ>>>(
        Ph, P8, Pl8, SS, Vh, V8, Vl8, SD, nullptr, CS_AV,
        out, nullptr, nullptr, nullptr, SD, D_);
}

// round 16
// speedup vs baseline: 1.0013x; 1.0004x over previous
#include <cuda_runtime.h>
#include <cuda_fp16.h>
#include <cstdint>

#define B_ 4
#define D_ 1024
#define S_ 2048

// ---------------------------------------------------------------------------
// Scratch. Each tensor X: Xh = fp16(X), X8 = s8(X/sh), Xl8 = s8((X-Xh)/sl)
// with sh = M'/127, sl = M'*2^-12/127, M' = per-tensor power-of-2 bound.
// ---------------------------------------------------------------------------
__device__ __half   g_xTh[(size_t)B_ * S_ * D_];
__device__ int8_t   g_xT8 [(size_t)B_ * S_ * D_];
__device__ int8_t   g_xTl8[(size_t)B_ * S_ * D_];
__device__ __half   g_Wqh[(size_t)D_ * D_];
__device__ int8_t   g_Wq8[(size_t)D_ * D_], g_Wql8[(size_t)D_ * D_];
__device__ __half   g_Wkh[(size_t)D_ * D_];
__device__ int8_t   g_Wk8[(size_t)D_ * D_], g_Wkl8[(size_t)D_ * D_];
__device__ __half   g_Wvh[(size_t)D_ * D_];
__device__ int8_t   g_Wv8[(size_t)D_ * D_], g_Wvl8[(size_t)D_ * D_];
__device__ __half   g_Qh[(size_t)B_ * S_ * D_];
__device__ int8_t   g_Q8[(size_t)B_ * S_ * D_], g_Ql8[(size_t)B_ * S_ * D_];
__device__ __half   g_Kh[(size_t)B_ * S_ * D_];
__device__ int8_t   g_K8[(size_t)B_ * S_ * D_], g_Kl8[(size_t)B_ * S_ * D_];
__device__ __half   g_Vh[(size_t)B_ * D_ * S_];
__device__ int8_t   g_V8[(size_t)B_ * D_ * S_], g_Vl8[(size_t)B_ * D_ * S_];
__device__ float    g_S [(size_t)B_ * S_ * S_];
__device__ __half   g_Ph[(size_t)B_ * S_ * S_];
__device__ int8_t   g_P8[(size_t)B_ * S_ * S_], g_Pl8[(size_t)B_ * S_ * S_];

// ---------------------------------------------------------------------------
// PTX helpers
// ---------------------------------------------------------------------------
__device__ __forceinline__ uint32_t smem_to_u32(const void* p) {
    uint32_t a;
    asm("{ .reg .u64 t; cvta.to.shared.u64 t, %1; cvt.u32.u64 %0, t; }"
        : "=r"(a) : "l"(p));
    return a;
}

#define CP_ASYNC16(dst_u32, src_ptr) \
    asm volatile("cp.async.cg.shared.global [%0], [%1], 16;" \
                 :: "r"(dst_u32), "l"(src_ptr) : "memory")

#define CP_COMMIT() asm volatile("cp.async.commit_group;" ::: "memory")

#define CP_WAIT(N) asm volatile("cp.async.wait_group %0;" :: "n"(N) : "memory")

#define LDSM4(R, addr) \
    asm volatile("ldmatrix.sync.aligned.m8n8.x4.shared.b16 {%0,%1,%2,%3}, [%4];" \
                 : "=r"((R)[0]), "=r"((R)[1]), "=r"((R)[2]), "=r"((R)[3]) \
                 : "r"(addr))

#define MMA16816(D, A, Bf) \
    asm("mma.sync.aligned.m16n8k16.row.col.f32.f16.f16.f32 " \
        "{%0,%1,%2,%3}, {%4,%5,%6,%7}, {%8,%9}, {%0,%1,%2,%3};" \
        : "+f"((D)[0]), "+f"((D)[1]), "+f"((D)[2]), "+f"((D)[3]) \
        : "r"((A)[0]), "r"((A)[1]), "r"((A)[2]), "r"((A)[3]), \
          "r"((Bf)[0]), "r"((Bf)[1]))

#define MMAI8(D, A, Bf) \
    asm("mma.sync.aligned.m16n8k32.row.col.s32.s8.s8.s32 " \
        "{%0,%1,%2,%3}, {%4,%5,%6,%7}, {%8,%9}, {%0,%1,%2,%3};" \
        : "+r"((D)[0]), "+r"((D)[1]), "+r"((D)[2]), "+r"((D)[3]) \
        : "r"((A)[0]), "r"((A)[1]), "r"((A)[2]), "r"((A)[3]), \
          "r"((Bf)[0]), "r"((Bf)[1]))

__device__ __forceinline__ int8_t q8(float v, float s_inv) {
    int i = __float2int_rn(v * s_inv);
    i = max(-127, min(127, i));
    return (int8_t)i;
}

// 3-form split: fp16 hi; s8 of value (scale inv hi_inv); s8 of residual
// (scale inv lo_inv = hi_inv * 4096).
__device__ __forceinline__ void split3i(float v, float hi_inv, float lo_inv,
                                        __half& h, int8_t& f8, int8_t& fl8) {
    h = __float2half_rn(v);
    f8 = q8(v, hi_inv);
    fl8 = q8(v - __half2float(h), lo_inv);
}

// ---------------------------------------------------------------------------
// GEMM: D[m,n] = sum_k A[m,k]*B[n,k]
//   acc_hi += Ah(fp16)*Bh(fp16)            [2x m16n8k16]
//   acc_lo += A8l*B8 + A8*B8l  (s8, s32)   [2x m16n8k32, ONE accumulator]
//   v = acc_hi + (float)acc_lo * CSCALE    (CSCALE = sAl*sBh = sAh*sBl)
// MODE 0: 3-form out +bias[n]; MODE 1: 3-form out +bias[m];
// MODE 2: fp32 out * 1/32; MODE 3: fp32 out
// CTA 128x64, 8 warps (4m x 2n), warp tile 32x32. 3-stage cp.async.
// fp16 pitch 80B; int8 pitch 48B. Layout identical to round-11 (proven).
// ---------------------------------------------------------------------------
#define SM_AH  0
#define SM_BH  10240
#define SM_A8  15360
#define SM_AL8 21504
#define SM_B8  27648
#define SM_BL8 30720
#define STAGE_BYTES 33792
#define NSTAGE 3

template <int KEL, int MODE>
__global__ __launch_bounds__(256, 2) void tc_gemm(
    const __half* __restrict__ Ah, const int8_t* __restrict__ A8,
    const int8_t* __restrict__ Al8, size_t sA,
    const __half* __restrict__ Bh, const int8_t* __restrict__ B8,
    const int8_t* __restrict__ Bl8, size_t sB,
    const float* __restrict__ bias, float cscale,
    float* __restrict__ outF,
    __half* __restrict__ outH, int8_t* __restrict__ out8,
    int8_t* __restrict__ outL8,
    size_t sO, int ldo)
{
    extern __shared__ char smem[];
    const uint32_t smem_base = smem_to_u32(smem);
    const int tid = threadIdx.x;
    const int wid = tid >> 5;
    const int lid = tid & 31;
    const int wm = wid >> 1;
    const int wn = wid & 1;
    const int b = blockIdx.z;
    const int m0 = blockIdx.y * 128;
    const int n0 = blockIdx.x * 64;

    Ah += (size_t)b * sA; A8 += (size_t)b * sA; Al8 += (size_t)b * sA;
    Bh += (size_t)b * sB; B8 += (size_t)b * sB; Bl8 += (size_t)b * sB;

    float acc_hi[2][4][4];
    int   acc_lo[2][4][4];
    #pragma unroll
    for (int i = 0; i < 2; ++i)
        #pragma unroll
        for (int j = 0; j < 4; ++j)
            #pragma unroll
            for (int k = 0; k < 4; ++k) { acc_hi[i][j][k] = 0.f; acc_lo[i][j][k] = 0; }

    constexpr int NC = KEL / 32;

    auto load_chunk = [&](int c) {
        const int koff = c * 32;
        const uint32_t sb = smem_base + (uint32_t)(c % NSTAGE) * STAGE_BYTES;
        #pragma unroll
        for (int i = 0; i < 2; ++i) {               // fp16 Ah
            const int idx = tid + i * 256;
            const int row = idx >> 2, c16 = idx & 3;
            CP_ASYNC16(sb + SM_AH + row * 80 + c16 * 16,
                       Ah + (size_t)(m0 + row) * KEL + koff + c16 * 8);
        }
        {                                           // fp16 Bh
            const int row = tid >> 2, c16 = tid & 3;
            CP_ASYNC16(sb + SM_BH + row * 80 + c16 * 16,
                       Bh + (size_t)(n0 + row) * KEL + koff + c16 * 8);
        }
        {                                           // s8 A8 + Al8
            const int row = tid >> 1, c16 = tid & 1;
            const size_t ga = (size_t)(m0 + row) * KEL + koff + c16 * 16;
            CP_ASYNC16(sb + SM_A8 + row * 48 + c16 * 16, A8 + ga);
            CP_ASYNC16(sb + SM_AL8 + row * 48 + c16 * 16, Al8 + ga);
        }
        {                                           // s8 B8 / Bl8
            const int t = tid & 127;
            const int row = t >> 1, c16 = t & 1;
            const size_t gb = (size_t)(n0 + row) * KEL + koff + c16 * 16;
            if (tid < 128)
                CP_ASYNC16(sb + SM_B8 + row * 48 + c16 * 16, B8 + gb);
            else
                CP_ASYNC16(sb + SM_BL8 + row * 48 + c16 * 16, Bl8 + gb);
        }
        CP_COMMIT();
    };

    load_chunk(0);
    load_chunk(1);

    const int rowA = wm * 32 + (lid & 15);
    const int rowB = wn * 32 + (lid & 15);
    const uint32_t kb = (uint32_t)((lid >> 4) * 16);

    const int g = lid >> 3;
    const uint32_t a8_lane = (uint32_t)((((g & 1) * 8) + (lid & 7)) * 48 + (g >> 1) * 16);
    const uint32_t b8_lane = (uint32_t)((((g >> 1) * 8) + (lid & 7)) * 48 + (g & 1) * 16);

    #pragma unroll 1
    for (int c = 0; c < NC; ++c) {
        if (c + 1 < NC) { CP_WAIT(1); } else { CP_WAIT(0); }
        __syncthreads();
        if (c + 2 < NC) load_chunk(c + 2);

        const uint32_t sb = smem_base + (uint32_t)(c % NSTAGE) * STAGE_BYTES;

        // ---- fp16 hi phase ----
        #pragma unroll
        for (int ks = 0; ks < 2; ++ks) {
            const uint32_t kbyte = (uint32_t)(ks * 32) + kb;
            uint32_t ah[2][4];
            #pragma unroll
            for (int mt = 0; mt < 2; ++mt)
                LDSM4(ah[mt], sb + SM_AH + (uint32_t)((rowA + mt * 16) * 80) + kbyte);
            uint32_t bh[4][2];
            #pragma unroll
            for (int np = 0; np < 2; ++np) {
                uint32_t t4[4];
                LDSM4(t4, sb + SM_BH + (uint32_t)((rowB + np * 16) * 80) + kbyte);
                bh[2 * np][0] = t4[0]; bh[2 * np][1] = t4[2];
                bh[2 * np + 1][0] = t4[1]; bh[2 * np + 1][1] = t4[3];
            }
            #pragma unroll
            for (int mt = 0; mt < 2; ++mt)
                #pragma unroll
                for (int nt = 0; nt < 4; ++nt)
                    MMA16816(acc_hi[mt][nt], ah[mt], bh[nt]);
        }

        // ---- int8 correction phase: acc_lo += A8l*B8 + A8*B8l ----
        {
            uint32_t a8h[2][4], a8l[2][4];
            #pragma unroll
            for (int mt = 0; mt < 2; ++mt) {
                const uint32_t base = (uint32_t)((wm * 32 + mt * 16) * 48) + a8_lane;
                LDSM4(a8h[mt], sb + SM_A8 + base);
                LDSM4(a8l[mt], sb + SM_AL8 + base);
            }
            uint32_t b8h[4][2], b8l[4][2];
            #pragma unroll
            for (int np = 0; np < 2; ++np) {
                const uint32_t base = (uint32_t)((wn * 32 + np * 16) * 48) + b8_lane;
                uint32_t t4[4];
                LDSM4(t4, sb + SM_B8 + base);
                b8h[2 * np][0] = t4[0]; b8h[2 * np][1] = t4[1];
                b8h[2 * np + 1][0] = t4[2]; b8h[2 * np + 1][1] = t4[3];
                LDSM4(t4, sb + SM_BL8 + base);
                b8l[2 * np][0] = t4[0]; b8l[2 * np][1] = t4[1];
                b8l[2 * np + 1][0] = t4[2]; b8l[2 * np + 1][1] = t4[3];
            }
            #pragma unroll
            for (int mt = 0; mt < 2; ++mt)
                #pragma unroll
                for (int nt = 0; nt < 4; ++nt)
                    MMAI8(acc_lo[mt][nt], a8l[mt], b8h[nt]);
            #pragma unroll
            for (int mt = 0; mt < 2; ++mt)
                #pragma unroll
                for (int nt = 0; nt < 4; ++nt)
                    MMAI8(acc_lo[mt][nt], a8h[mt], b8l[nt]);
        }
    }

    // ---- epilogue ----
    const int gq = lid >> 2, t4i = lid & 3;
    // Q/K/V outputs use M'=4: hi_inv = 127/4, lo_inv = 127*4096/4
    const float OH_INV = 31.75f, OL_INV = 130048.0f;
    #pragma unroll
    for (int mt = 0; mt < 2; ++mt) {
        const int m = m0 + wm * 32 + mt * 16 + gq;
        float bm0 = 0.f, bm8 = 0.f;
        if (MODE == 1) { bm0 = bias[m]; bm8 = bias[m + 8]; }
        #pragma unroll
        for (int nt = 0; nt < 4; ++nt) {
            const int n = n0 + wn * 32 + nt * 8 + 2 * t4i;
            float v0 = acc_hi[mt][nt][0] + (float)acc_lo[mt][nt][0] * cscale;
            float v1 = acc_hi[mt][nt][1] + (float)acc_lo[mt][nt][1] * cscale;
            float v2 = acc_hi[mt][nt][2] + (float)acc_lo[mt][nt][2] * cscale;
            float v3 = acc_hi[mt][nt][3] + (float)acc_lo[mt][nt][3] * cscale;
            if (MODE == 0) {
                const float bn0 = bias[n], bn1 = bias[n + 1];
                v0 += bn0; v1 += bn1; v2 += bn0; v3 += bn1;
            } else if (MODE == 1) {
                v0 += bm0; v1 += bm0; v2 += bm8; v3 += bm8;
            } else if (MODE == 2) {
                v0 *= 0.03125f; v1 *= 0.03125f; v2 *= 0.03125f; v3 *= 0.03125f;
            }
            if (MODE == 0 || MODE == 1) {
                __half h0, h1; int8_t f0, f1, l0, l1;
                const size_t o0 = (size_t)b * sO + (size_t)m * ldo + n;
                split3i(v0, OH_INV, OL_INV, h0, f0, l0);
                split3i(v1, OH_INV, OL_INV, h1, f1, l1);
                { __half2 hh; hh.x = h0; hh.y = h1;
                  *(__half2*)(outH + o0) = hh;
                  char2 u8; u8.x = f0; u8.y = f1; *(char2*)(out8 + o0) = u8;
                  char2 ul; ul.x = l0; ul.y = l1; *(char2*)(outL8 + o0) = ul; }
                const size_t o8 = (size_t)b * sO + (size_t)(m + 8) * ldo + n;
                split3i(v2, OH_INV, OL_INV, h0, f0, l0);
                split3i(v3, OH_INV, OL_INV, h1, f1, l1);
                { __half2 hh; hh.x = h0; hh.y = h1;
                  *(__half2*)(outH + o8) = hh;
                  char2 u8; u8.x = f0; u8.y = f1; *(char2*)(out8 + o8) = u8;
                  char2 ul; ul.x = l0; ul.y = l1; *(char2*)(outL8 + o8) = ul; }
            } else {
                float2 f0; f0.x = v0; f0.y = v1;
                float2 f8; f8.x = v2; f8.y = v3;
                *(float2*)(outF + (size_t)b * sO + (size_t)m * ldo + n) = f0;
                *(float2*)(outF + (size_t)b * sO + (size_t)(m + 8) * ldo + n) = f8;
            }
        }
    }
}

// ---------------------------------------------------------------------------
// Weights: M' = 2^-5. hi_inv = 127*32, lo_inv = 127*4096*32
// ---------------------------------------------------------------------------
__global__ __launch_bounds__(256) void wsplit3_kernel(
    const float* __restrict__ w0, const float* __restrict__ w1,
    const float* __restrict__ w2,
    __half* __restrict__ h0, int8_t* __restrict__ f0, int8_t* __restrict__ l0,
    __half* __restrict__ h1, int8_t* __restrict__ f1, int8_t* __restrict__ l1,
    __half* __restrict__ h2, int8_t* __restrict__ f2, int8_t* __restrict__ l2)
{
    const int which = blockIdx.y;
    const float* w = (which == 0) ? w0 : (which == 1) ? w1 : w2;
    __half* h = (which == 0) ? h0 : (which == 1) ? h1 : h2;
    int8_t* f = (which == 0) ? f0 : (which == 1) ? f1 : f2;
    int8_t* l = (which == 0) ? l0 : (which == 1) ? l1 : l2;
    const int n = D_ * D_;
    const float HI = 127.0f * 32.0f, LO = 127.0f * 4096.0f * 32.0f;
    for (int i = blockIdx.x * 256 + threadIdx.x; i < n; i += gridDim.x * 256) {
        __half hi; int8_t v8, vl8;
        split3i(w[i], HI, LO, hi, v8, vl8);
        h[i] = hi; f[i] = v8; l[i] = vl8;
    }
}

// ---------------------------------------------------------------------------
// x transpose+split: M' = 8. hi_inv = 127/8, lo_inv = 127*512
// ---------------------------------------------------------------------------
__global__ __launch_bounds__(256) void xpose_split_kernel(const float* __restrict__ x)
{
    __shared__ float t[32][33];
    const int b = blockIdx.z;
    const int d0 = blockIdx.y * 32;
    const int s0 = blockIdx.x * 32;
    const int tx = threadIdx.x & 31;
    const int ty = threadIdx.x >> 5;
    const float* X = x + (size_t)b * D_ * S_;
    const float HI = 127.0f / 8.0f, LO = 127.0f * 512.0f;

    #pragma unroll
    for (int i = 0; i < 4; ++i)
        t[ty + i * 8][tx] = X[(size_t)(d0 + ty + i * 8) * S_ + s0 + tx];
    __syncthreads();
    #pragma unroll
    for (int i = 0; i < 4; ++i) {
        const int s = s0 + ty + i * 8;
        const int d = d0 + tx;
        const float v = t[tx][ty + i * 8];
        __half hi; int8_t v8, vl8;
        split3i(v, HI, LO, hi, v8, vl8);
        const size_t idx = (size_t)b * S_ * D_ + (size_t)s * D_ + d;
        g_xTh[idx] = hi;
        g_xT8[idx] = v8;
        g_xTl8[idx] = vl8;
    }
}

// ---------------------------------------------------------------------------
// softmax: P in [0,1], M' = 1. hi_inv = 127, lo_inv = 127*4096
// ---------------------------------------------------------------------------
__global__ __launch_bounds__(256) void softmax_split_kernel()
{
    const size_t row = blockIdx.x;
    const float* __restrict__ p = g_S + row * S_;
    __half* __restrict__ ph = g_Ph + row * S_;
    int8_t* __restrict__ p8 = g_P8 + row * S_;
    int8_t* __restrict__ pl8 = g_Pl8 + row * S_;
    const int tid = threadIdx.x;
    const float HI = 127.0f, LO = 127.0f * 4096.0f;

    float v[8];
    #pragma unroll
    for (int i = 0; i < 8; ++i) v[i] = p[i * 256 + tid];

    float m = v[0];
    #pragma unroll
    for (int i = 1; i < 8; ++i) m = fmaxf(m, v[i]);

    __shared__ float red[8];
    #pragma unroll
    for (int o = 16; o > 0; o >>= 1)
        m = fmaxf(m, __shfl_xor_sync(0xffffffffu, m, o));
    if ((tid & 31) == 0) red[tid >> 5] = m;
    __syncthreads();
    m = red[0];
    #pragma unroll
    for (int i = 1; i < 8; ++i) m = fmaxf(m, red[i]);
    __syncthreads();

    float s = 0.f;
    #pragma unroll
    for (int i = 0; i < 8; ++i) { v[i] = expf(v[i] - m); s += v[i]; }
    #pragma unroll
    for (int o = 16; o > 0; o >>= 1)
        s += __shfl_xor_sync(0xffffffffu, s, o);
    if ((tid & 31) == 0) red[tid >> 5] = s;
    __syncthreads();
    s = 0.f;
    #pragma unroll
    for (int i = 0; i < 8; ++i) s += red[i];

    const float inv = 1.0f / s;
    #pragma unroll
    for (int i = 0; i < 8; ++i) {
        __half hi; int8_t v8, vl8;
        split3i(v[i] * inv, HI, LO, hi, v8, vl8);
        ph[i * 256 + tid] = hi;
        p8[i * 256 + tid] = v8;
        pl8[i * 256 + tid] = vl8;
    }
}

// ---------------------------------------------------------------------------
extern "C" void kernel_launch(void* const* d_in, const int* in_sizes, int n_in,
                              void* d_out, int out_size)
{
    const float* x  = (const float*)d_in[0];
    const float* Wq = (const float*)d_in[1];
    const float* bq = (const float*)d_in[2];
    const float* Wk = (const float*)d_in[3];
    const float* bk = (const float*)d_in[4];
    const float* Wv = (const float*)d_in[5];
    const float* bv = (const float*)d_in[6];
    float* out = (float*)d_out;

    const int SMEM_SZ = NSTAGE * STAGE_BYTES;   // 101376

    cudaFuncSetAttribute(tc_gemm<1024, 0>, cudaFuncAttributeMaxDynamicSharedMemorySize, SMEM_SZ);
    cudaFuncSetAttribute(tc_gemm<1024, 1>, cudaFuncAttributeMaxDynamicSharedMemorySize, SMEM_SZ);
    cudaFuncSetAttribute(tc_gemm<1024, 2>, cudaFuncAttributeMaxDynamicSharedMemorySize, SMEM_SZ);
    cudaFuncSetAttribute(tc_gemm<2048, 3>, cudaFuncAttributeMaxDynamicSharedMemorySize, SMEM_SZ);

    __half *xTh, *Wqh, *Wkh, *Wvh, *Qh, *Kh, *Vh, *Ph;
    int8_t *xT8, *xTl8, *Wq8, *Wql8, *Wk8, *Wkl8, *Wv8, *Wvl8;
    int8_t *Q8, *Ql8, *K8, *Kl8, *V8, *Vl8, *P8, *Pl8;
    float* Sc;
    cudaGetSymbolAddress((void**)&xTh, g_xTh);
    cudaGetSymbolAddress((void**)&xT8, g_xT8);
    cudaGetSymbolAddress((void**)&xTl8, g_xTl8);
    cudaGetSymbolAddress((void**)&Wqh, g_Wqh);
    cudaGetSymbolAddress((void**)&Wq8, g_Wq8);
    cudaGetSymbolAddress((void**)&Wql8, g_Wql8);
    cudaGetSymbolAddress((void**)&Wkh, g_Wkh);
    cudaGetSymbolAddress((void**)&Wk8, g_Wk8);
    cudaGetSymbolAddress((void**)&Wkl8, g_Wkl8);
    cudaGetSymbolAddress((void**)&Wvh, g_Wvh);
    cudaGetSymbolAddress((void**)&Wv8, g_Wv8);
    cudaGetSymbolAddress((void**)&Wvl8, g_Wvl8);
    cudaGetSymbolAddress((void**)&Qh, g_Qh);
    cudaGetSymbolAddress((void**)&Q8, g_Q8);
    cudaGetSymbolAddress((void**)&Ql8, g_Ql8);
    cudaGetSymbolAddress((void**)&Kh, g_Kh);
    cudaGetSymbolAddress((void**)&K8, g_K8);
    cudaGetSymbolAddress((void**)&Kl8, g_Kl8);
    cudaGetSymbolAddress((void**)&Vh, g_Vh);
    cudaGetSymbolAddress((void**)&V8, g_V8);
    cudaGetSymbolAddress((void**)&Vl8, g_Vl8);
    cudaGetSymbolAddress((void**)&Ph, g_Ph);
    cudaGetSymbolAddress((void**)&P8, g_P8);
    cudaGetSymbolAddress((void**)&Pl8, g_Pl8);
    cudaGetSymbolAddress((void**)&Sc, g_S);

    const size_t SD = (size_t)S_ * D_;
    const size_t SS = (size_t)S_ * S_;

    // CSCALE = sAl*sBh = (M'A*2^-12/127)*(M'B/127)
    const float CS_PROJ = (8.0f / 4096.0f / 127.0f) * (0.03125f / 127.0f);
    const float CS_QK   = (4.0f / 4096.0f / 127.0f) * (4.0f / 127.0f);
    const float CS_AV   = (1.0f / 4096.0f / 127.0f) * (4.0f / 127.0f);

    // 1) operand preparation
    wsplit3_kernel<<<dim3(64, 3), 256>>>(Wq, Wk, Wv,
                                         Wqh, Wq8, Wql8,
                                         Wkh, Wk8, Wkl8,
                                         Wvh, Wv8, Wvl8);
    xpose_split_kernel<<<dim3(S_ / 32, D_ / 32, B_), 256>>>(x);

    // 2) projections
    tc_gemm<1024, 0><<<dim3(D_ / 64, S_ / 128, B_), 256, SMEM_SZ>>>(
        xTh, xT8, xTl8, SD, Wqh, Wq8, Wql8, 0, bq, CS_PROJ,
        nullptr, Qh, Q8, Ql8, SD, D_);
    tc_gemm<1024, 0><<<dim3(D_ / 64, S_ / 128, B_), 256, SMEM_SZ>>>(
        xTh, xT8, xTl8, SD, Wkh, Wk8, Wkl8, 0, bk, CS_PROJ,
        nullptr, Kh, K8, Kl8, SD, D_);
    tc_gemm<1024, 1><<<dim3(S_ / 64, D_ / 128, B_), 256, SMEM_SZ>>>(
        Wvh, Wv8, Wvl8, 0, xTh, xT8, xTl8, SD, bv, CS_PROJ,
        nullptr, Vh, V8, Vl8, SD, S_);

    // 3) scores
    tc_gemm<1024, 2><<<dim3(S_ / 64, S_ / 128, B_), 256, SMEM_SZ>>>(
        Qh, Q8, Ql8, SD, Kh, K8, Kl8, SD, nullptr, CS_QK,
        Sc, nullptr, nullptr, nullptr, SS, S_);

    // 4) softmax
    softmax_split_kernel<<<B_ * S_, 256>>>();

    // 5) out = P.V
    tc_gemm<2048, 3><<<dim3(D_ / 64, S_ / 128, B_), 256, SMEM_SZ>>>(
        Ph, P8, Pl8, SS, Vh, V8, Vl8, SD, nullptr, CS_AV,
        out, nullptr, nullptr, nullptr, SD, D_);
}

// round 17
// speedup vs baseline: 1.0014x; 1.0000x over previous
#include <cuda_runtime.h>
#include <cuda_fp16.h>
#include <cstdint>

#define B_ 4
#define D_ 1024
#define S_ 2048

// ---------------------------------------------------------------------------
// Scratch. Each tensor X: Xh = fp16(X), X8 = s8(X/sh), Xl8 = s8((X-Xh)/sl)
// with sh = M'/127, sl = M'*2^-12/127, M' = per-tensor power-of-2 bound.
// ---------------------------------------------------------------------------
__device__ __half   g_xTh[(size_t)B_ * S_ * D_];
__device__ int8_t   g_xT8 [(size_t)B_ * S_ * D_];
__device__ int8_t   g_xTl8[(size_t)B_ * S_ * D_];
__device__ __half   g_Wqh[(size_t)D_ * D_];
__device__ int8_t   g_Wq8[(size_t)D_ * D_], g_Wql8[(size_t)D_ * D_];
__device__ __half   g_Wkh[(size_t)D_ * D_];
__device__ int8_t   g_Wk8[(size_t)D_ * D_], g_Wkl8[(size_t)D_ * D_];
__device__ __half   g_Wvh[(size_t)D_ * D_];
__device__ int8_t   g_Wv8[(size_t)D_ * D_], g_Wvl8[(size_t)D_ * D_];
__device__ __half   g_Qh[(size_t)B_ * S_ * D_];
__device__ int8_t   g_Q8[(size_t)B_ * S_ * D_], g_Ql8[(size_t)B_ * S_ * D_];
__device__ __half   g_Kh[(size_t)B_ * S_ * D_];
__device__ int8_t   g_K8[(size_t)B_ * S_ * D_], g_Kl8[(size_t)B_ * S_ * D_];
__device__ __half   g_Vh[(size_t)B_ * D_ * S_];
__device__ int8_t   g_V8[(size_t)B_ * D_ * S_], g_Vl8[(size_t)B_ * D_ * S_];
__device__ float    g_S [(size_t)B_ * S_ * S_];
__device__ __half   g_Ph[(size_t)B_ * S_ * S_];
__device__ int8_t   g_P8[(size_t)B_ * S_ * S_], g_Pl8[(size_t)B_ * S_ * S_];

// ---------------------------------------------------------------------------
// PTX helpers
// ---------------------------------------------------------------------------
__device__ __forceinline__ uint32_t smem_to_u32(const void* p) {
    uint32_t a;
    asm("{ .reg .u64 t; cvta.to.shared.u64 t, %1; cvt.u32.u64 %0, t; }"
        : "=r"(a) : "l"(p));
    return a;
}

#define CP_ASYNC16(dst_u32, src_ptr) \
    asm volatile("cp.async.cg.shared.global [%0], [%1], 16;" \
                 :: "r"(dst_u32), "l"(src_ptr) : "memory")

#define CP_COMMIT() asm volatile("cp.async.commit_group;" ::: "memory")

#define CP_WAIT(N) asm volatile("cp.async.wait_group %0;" :: "n"(N) : "memory")

#define LDSM4(R, addr) \
    asm volatile("ldmatrix.sync.aligned.m8n8.x4.shared.b16 {%0,%1,%2,%3}, [%4];" \
                 : "=r"((R)[0]), "=r"((R)[1]), "=r"((R)[2]), "=r"((R)[3]) \
                 : "r"(addr))

#define MMA16816(D, A, Bf) \
    asm("mma.sync.aligned.m16n8k16.row.col.f32.f16.f16.f32 " \
        "{%0,%1,%2,%3}, {%4,%5,%6,%7}, {%8,%9}, {%0,%1,%2,%3};" \
        : "+f"((D)[0]), "+f"((D)[1]), "+f"((D)[2]), "+f"((D)[3]) \
        : "r"((A)[0]), "r"((A)[1]), "r"((A)[2]), "r"((A)[3]), \
          "r"((Bf)[0]), "r"((Bf)[1]))

#define MMAI8(D, A, Bf) \
    asm("mma.sync.aligned.m16n8k32.row.col.s32.s8.s8.s32 " \
        "{%0,%1,%2,%3}, {%4,%5,%6,%7}, {%8,%9}, {%0,%1,%2,%3};" \
        : "+r"((D)[0]), "+r"((D)[1]), "+r"((D)[2]), "+r"((D)[3]) \
        : "r"((A)[0]), "r"((A)[1]), "r"((A)[2]), "r"((A)[3]), \
          "r"((Bf)[0]), "r"((Bf)[1]))

__device__ __forceinline__ int8_t q8(float v, float s_inv) {
    int i = __float2int_rn(v * s_inv);
    i = max(-127, min(127, i));
    return (int8_t)i;
}

// 3-form split: fp16 hi; s8 of value (scale inv hi_inv); s8 of residual
// (scale inv lo_inv = hi_inv * 4096).
__device__ __forceinline__ void split3i(float v, float hi_inv, float lo_inv,
                                        __half& h, int8_t& f8, int8_t& fl8) {
    h = __float2half_rn(v);
    f8 = q8(v, hi_inv);
    fl8 = q8(v - __half2float(h), lo_inv);
}

// ---------------------------------------------------------------------------
// GEMM: D[m,n] = sum_k A[m,k]*B[n,k]
//   acc_hi += Ah(fp16)*Bh(fp16)            [2x m16n8k16]
//   acc_lo += A8l*B8 + A8*B8l  (s8, s32)   [2x m16n8k32, ONE accumulator]
//   v = acc_hi + (float)acc_lo * CSCALE    (CSCALE = sAl*sBh = sAh*sBl)
// MODE 0: 3-form out +bias[n]; MODE 1: 3-form out +bias[m];
// MODE 2: fp32 out * 1/32; MODE 3: fp32 out
// CTA 128x64, 8 warps (4m x 2n), warp tile 32x32. 3-stage cp.async.
// fp16 pitch 80B; int8 pitch 48B. Layout identical to round-11 (proven).
// ---------------------------------------------------------------------------
#define SM_AH  0
#define SM_BH  10240
#define SM_A8  15360
#define SM_AL8 21504
#define SM_B8  27648
#define SM_BL8 30720
#define STAGE_BYTES 33792
#define NSTAGE 3

template <int KEL, int MODE>
__global__ __launch_bounds__(256, 2) void tc_gemm(
    const __half* __restrict__ Ah, const int8_t* __restrict__ A8,
    const int8_t* __restrict__ Al8, size_t sA,
    const __half* __restrict__ Bh, const int8_t* __restrict__ B8,
    const int8_t* __restrict__ Bl8, size_t sB,
    const float* __restrict__ bias, float cscale,
    float* __restrict__ outF,
    __half* __restrict__ outH, int8_t* __restrict__ out8,
    int8_t* __restrict__ outL8,
    size_t sO, int ldo)
{
    extern __shared__ char smem[];
    const uint32_t smem_base = smem_to_u32(smem);
    const int tid = threadIdx.x;
    const int wid = tid >> 5;
    const int lid = tid & 31;
    const int wm = wid >> 1;
    const int wn = wid & 1;
    const int b = blockIdx.z;
    const int m0 = blockIdx.y * 128;
    const int n0 = blockIdx.x * 64;

    Ah += (size_t)b * sA; A8 += (size_t)b * sA; Al8 += (size_t)b * sA;
    Bh += (size_t)b * sB; B8 += (size_t)b * sB; Bl8 += (size_t)b * sB;

    float acc_hi[2][4][4];
    int   acc_lo[2][4][4];
    #pragma unroll
    for (int i = 0; i < 2; ++i)
        #pragma unroll
        for (int j = 0; j < 4; ++j)
            #pragma unroll
            for (int k = 0; k < 4; ++k) { acc_hi[i][j][k] = 0.f; acc_lo[i][j][k] = 0; }

    constexpr int NC = KEL / 32;

    auto load_chunk = [&](int c) {
        const int koff = c * 32;
        const uint32_t sb = smem_base + (uint32_t)(c % NSTAGE) * STAGE_BYTES;
        #pragma unroll
        for (int i = 0; i < 2; ++i) {               // fp16 Ah
            const int idx = tid + i * 256;
            const int row = idx >> 2, c16 = idx & 3;
            CP_ASYNC16(sb + SM_AH + row * 80 + c16 * 16,
                       Ah + (size_t)(m0 + row) * KEL + koff + c16 * 8);
        }
        {                                           // fp16 Bh
            const int row = tid >> 2, c16 = tid & 3;
            CP_ASYNC16(sb + SM_BH + row * 80 + c16 * 16,
                       Bh + (size_t)(n0 + row) * KEL + koff + c16 * 8);
        }
        {                                           // s8 A8 + Al8
            const int row = tid >> 1, c16 = tid & 1;
            const size_t ga = (size_t)(m0 + row) * KEL + koff + c16 * 16;
            CP_ASYNC16(sb + SM_A8 + row * 48 + c16 * 16, A8 + ga);
            CP_ASYNC16(sb + SM_AL8 + row * 48 + c16 * 16, Al8 + ga);
        }
        {                                           // s8 B8 / Bl8
            const int t = tid & 127;
            const int row = t >> 1, c16 = t & 1;
            const size_t gb = (size_t)(n0 + row) * KEL + koff + c16 * 16;
            if (tid < 128)
                CP_ASYNC16(sb + SM_B8 + row * 48 + c16 * 16, B8 + gb);
            else
                CP_ASYNC16(sb + SM_BL8 + row * 48 + c16 * 16, Bl8 + gb);
        }
        CP_COMMIT();
    };

    load_chunk(0);
    load_chunk(1);

    const int rowA = wm * 32 + (lid & 15);
    const int rowB = wn * 32 + (lid & 15);
    const uint32_t kb = (uint32_t)((lid >> 4) * 16);

    const int g = lid >> 3;
    const uint32_t a8_lane = (uint32_t)((((g & 1) * 8) + (lid & 7)) * 48 + (g >> 1) * 16);
    const uint32_t b8_lane = (uint32_t)((((g >> 1) * 8) + (lid & 7)) * 48 + (g & 1) * 16);

    #pragma unroll 1
    for (int c = 0; c < NC; ++c) {
        if (c + 1 < NC) { CP_WAIT(1); } else { CP_WAIT(0); }
        __syncthreads();
        if (c + 2 < NC) load_chunk(c + 2);

        const uint32_t sb = smem_base + (uint32_t)(c % NSTAGE) * STAGE_BYTES;

        // ---- fp16 hi phase ----
        #pragma unroll
        for (int ks = 0; ks < 2; ++ks) {
            const uint32_t kbyte = (uint32_t)(ks * 32) + kb;
            uint32_t ah[2][4];
            #pragma unroll
            for (int mt = 0; mt < 2; ++mt)
                LDSM4(ah[mt], sb + SM_AH + (uint32_t)((rowA + mt * 16) * 80) + kbyte);
            uint32_t bh[4][2];
            #pragma unroll
            for (int np = 0; np < 2; ++np) {
                uint32_t t4[4];
                LDSM4(t4, sb + SM_BH + (uint32_t)((rowB + np * 16) * 80) + kbyte);
                bh[2 * np][0] = t4[0]; bh[2 * np][1] = t4[2];
                bh[2 * np + 1][0] = t4[1]; bh[2 * np + 1][1] = t4[3];
            }
            #pragma unroll
            for (int mt = 0; mt < 2; ++mt)
                #pragma unroll
                for (int nt = 0; nt < 4; ++nt)
                    MMA16816(acc_hi[mt][nt], ah[mt], bh[nt]);
        }

        // ---- int8 correction phase: acc_lo += A8l*B8 + A8*B8l ----
        {
            uint32_t a8h[2][4], a8l[2][4];
            #pragma unroll
            for (int mt = 0; mt < 2; ++mt) {
                const uint32_t base = (uint32_t)((wm * 32 + mt * 16) * 48) + a8_lane;
                LDSM4(a8h[mt], sb + SM_A8 + base);
                LDSM4(a8l[mt], sb + SM_AL8 + base);
            }
            uint32_t b8h[4][2], b8l[4][2];
            #pragma unroll
            for (int np = 0; np < 2; ++np) {
                const uint32_t base = (uint32_t)((wn * 32 + np * 16) * 48) + b8_lane;
                uint32_t t4[4];
                LDSM4(t4, sb + SM_B8 + base);
                b8h[2 * np][0] = t4[0]; b8h[2 * np][1] = t4[1];
                b8h[2 * np + 1][0] = t4[2]; b8h[2 * np + 1][1] = t4[3];
                LDSM4(t4, sb + SM_BL8 + base);
                b8l[2 * np][0] = t4[0]; b8l[2 * np][1] = t4[1];
                b8l[2 * np + 1][0] = t4[2]; b8l[2 * np + 1][1] = t4[3];
            }
            #pragma unroll
            for (int mt = 0; mt < 2; ++mt)
                #pragma unroll
                for (int nt = 0; nt < 4; ++nt)
                    MMAI8(acc_lo[mt][nt], a8l[mt], b8h[nt]);
            #pragma unroll
            for (int mt = 0; mt < 2; ++mt)
                #pragma unroll
                for (int nt = 0; nt < 4; ++nt)
                    MMAI8(acc_lo[mt][nt], a8h[mt], b8l[nt]);
        }
    }

    // ---- epilogue ----
    const int gq = lid >> 2, t4i = lid & 3;
    // Q/K/V outputs use M'=4: hi_inv = 127/4, lo_inv = 127*4096/4
    const float OH_INV = 31.75f, OL_INV = 130048.0f;
    #pragma unroll
    for (int mt = 0; mt < 2; ++mt) {
        const int m = m0 + wm * 32 + mt * 16 + gq;
        float bm0 = 0.f, bm8 = 0.f;
        if (MODE == 1) { bm0 = bias[m]; bm8 = bias[m + 8]; }
        #pragma unroll
        for (int nt = 0; nt < 4; ++nt) {
            const int n = n0 + wn * 32 + nt * 8 + 2 * t4i;
            float v0 = acc_hi[mt][nt][0] + (float)acc_lo[mt][nt][0] * cscale;
            float v1 = acc_hi[mt][nt][1] + (float)acc_lo[mt][nt][1] * cscale;
            float v2 = acc_hi[mt][nt][2] + (float)acc_lo[mt][nt][2] * cscale;
            float v3 = acc_hi[mt][nt][3] + (float)acc_lo[mt][nt][3] * cscale;
            if (MODE == 0) {
                const float bn0 = bias[n], bn1 = bias[n + 1];
                v0 += bn0; v1 += bn1; v2 += bn0; v3 += bn1;
            } else if (MODE == 1) {
                v0 += bm0; v1 += bm0; v2 += bm8; v3 += bm8;
            } else if (MODE == 2) {
                v0 *= 0.03125f; v1 *= 0.03125f; v2 *= 0.03125f; v3 *= 0.03125f;
            }
            if (MODE == 0 || MODE == 1) {
                __half h0, h1; int8_t f0, f1, l0, l1;
                const size_t o0 = (size_t)b * sO + (size_t)m * ldo + n;
                split3i(v0, OH_INV, OL_INV, h0, f0, l0);
                split3i(v1, OH_INV, OL_INV, h1, f1, l1);
                { __half2 hh; hh.x = h0; hh.y = h1;
                  *(__half2*)(outH + o0) = hh;
                  char2 u8; u8.x = f0; u8.y = f1; *(char2*)(out8 + o0) = u8;
                  char2 ul; ul.x = l0; ul.y = l1; *(char2*)(outL8 + o0) = ul; }
                const size_t o8 = (size_t)b * sO + (size_t)(m + 8) * ldo + n;
                split3i(v2, OH_INV, OL_INV, h0, f0, l0);
                split3i(v3, OH_INV, OL_INV, h1, f1, l1);
                { __half2 hh; hh.x = h0; hh.y = h1;
                  *(__half2*)(outH + o8) = hh;
                  char2 u8; u8.x = f0; u8.y = f1; *(char2*)(out8 + o8) = u8;
                  char2 ul; ul.x = l0; ul.y = l1; *(char2*)(outL8 + o8) = ul; }
            } else {
                float2 f0; f0.x = v0; f0.y = v1;
                float2 f8; f8.x = v2; f8.y = v3;
                *(float2*)(outF + (size_t)b * sO + (size_t)m * ldo + n) = f0;
                *(float2*)(outF + (size_t)b * sO + (size_t)(m + 8) * ldo + n) = f8;
            }
        }
    }
}

// ---------------------------------------------------------------------------
// Weights: M' = 2^-5. hi_inv = 127*32, lo_inv = 127*4096*32
// ---------------------------------------------------------------------------
__global__ __launch_bounds__(256) void wsplit3_kernel(
    const float* __restrict__ w0, const float* __restrict__ w1,
    const float* __restrict__ w2,
    __half* __restrict__ h0, int8_t* __restrict__ f0, int8_t* __restrict__ l0,
    __half* __restrict__ h1, int8_t* __restrict__ f1, int8_t* __restrict__ l1,
    __half* __restrict__ h2, int8_t* __restrict__ f2, int8_t* __restrict__ l2)
{
    const int which = blockIdx.y;
    const float* w = (which == 0) ? w0 : (which == 1) ? w1 : w2;
    __half* h = (which == 0) ? h0 : (which == 1) ? h1 : h2;
    int8_t* f = (which == 0) ? f0 : (which == 1) ? f1 : f2;
    int8_t* l = (which == 0) ? l0 : (which == 1) ? l1 : l2;
    const int n = D_ * D_;
    const float HI = 127.0f * 32.0f, LO = 127.0f * 4096.0f * 32.0f;
    for (int i = blockIdx.x * 256 + threadIdx.x; i < n; i += gridDim.x * 256) {
        __half hi; int8_t v8, vl8;
        split3i(w[i], HI, LO, hi, v8, vl8);
        h[i] = hi; f[i] = v8; l[i] = vl8;
    }
}

// ---------------------------------------------------------------------------
// x transpose+split: M' = 8. hi_inv = 127/8, lo_inv = 127*512
// ---------------------------------------------------------------------------
__global__ __launch_bounds__(256) void xpose_split_kernel(const float* __restrict__ x)
{
    __shared__ float t[32][33];
    const int b = blockIdx.z;
    const int d0 = blockIdx.y * 32;
    const int s0 = blockIdx.x * 32;
    const int tx = threadIdx.x & 31;
    const int ty = threadIdx.x >> 5;
    const float* X = x + (size_t)b * D_ * S_;
    const float HI = 127.0f / 8.0f, LO = 127.0f * 512.0f;

    #pragma unroll
    for (int i = 0; i < 4; ++i)
        t[ty + i * 8][tx] = X[(size_t)(d0 + ty + i * 8) * S_ + s0 + tx];
    __syncthreads();
    #pragma unroll
    for (int i = 0; i < 4; ++i) {
        const int s = s0 + ty + i * 8;
        const int d = d0 + tx;
        const float v = t[tx][ty + i * 8];
        __half hi; int8_t v8, vl8;
        split3i(v, HI, LO, hi, v8, vl8);
        const size_t idx = (size_t)b * S_ * D_ + (size_t)s * D_ + d;
        g_xTh[idx] = hi;
        g_xT8[idx] = v8;
        g_xTl8[idx] = vl8;
    }
}

// ---------------------------------------------------------------------------
// softmax: P in [0,1], M' = 1. hi_inv = 127, lo_inv = 127*4096
// ---------------------------------------------------------------------------
__global__ __launch_bounds__(256) void softmax_split_kernel()
{
    const size_t row = blockIdx.x;
    const float* __restrict__ p = g_S + row * S_;
    __half* __restrict__ ph = g_Ph + row * S_;
    int8_t* __restrict__ p8 = g_P8 + row * S_;
    int8_t* __restrict__ pl8 = g_Pl8 + row * S_;
    const int tid = threadIdx.x;
    const float HI = 127.0f, LO = 127.0f * 4096.0f;

    float v[8];
    #pragma unroll
    for (int i = 0; i < 8; ++i) v[i] = p[i * 256 + tid];

    float m = v[0];
    #pragma unroll
    for (int i = 1; i < 8; ++i) m = fmaxf(m, v[i]);

    __shared__ float red[8];
    #pragma unroll
    for (int o = 16; o > 0; o >>= 1)
        m = fmaxf(m, __shfl_xor_sync(0xffffffffu, m, o));
    if ((tid & 31) == 0) red[tid >> 5] = m;
    __syncthreads();
    m = red[0];
    #pragma unroll
    for (int i = 1; i < 8; ++i) m = fmaxf(m, red[i]);
    __syncthreads();

    float s = 0.f;
    #pragma unroll
    for (int i = 0; i < 8; ++i) { v[i] = expf(v[i] - m); s += v[i]; }
    #pragma unroll
    for (int o = 16; o > 0; o >>= 1)
        s += __shfl_xor_sync(0xffffffffu, s, o);
    if ((tid & 31) == 0) red[tid >> 5] = s;
    __syncthreads();
    s = 0.f;
    #pragma unroll
    for (int i = 0; i < 8; ++i) s += red[i];

    const float inv = 1.0f / s;
    #pragma unroll
    for (int i = 0; i < 8; ++i) {
        __half hi; int8_t v8, vl8;
        split3i(v[i] * inv, HI, LO, hi, v8, vl8);
        ph[i * 256 + tid] = hi;
        p8[i * 256 + tid] = v8;
        pl8[i * 256 + tid] = vl8;
    }
}

// ---------------------------------------------------------------------------
extern "C" void kernel_launch(void* const* d_in, const int* in_sizes, int n_in,
                              void* d_out, int out_size)
{
    const float* x  = (const float*)d_in[0];
    const float* Wq = (const float*)d_in[1];
    const float* bq = (const float*)d_in[2];
    const float* Wk = (const float*)d_in[3];
    const float* bk = (const float*)d_in[4];
    const float* Wv = (const float*)d_in[5];
    const float* bv = (const float*)d_in[6];
    float* out = (float*)d_out;

    const int SMEM_SZ = NSTAGE * STAGE_BYTES;   // 101376

    cudaFuncSetAttribute(tc_gemm<1024, 0>, cudaFuncAttributeMaxDynamicSharedMemorySize, SMEM_SZ);
    cudaFuncSetAttribute(tc_gemm<1024, 1>, cudaFuncAttributeMaxDynamicSharedMemorySize, SMEM_SZ);
    cudaFuncSetAttribute(tc_gemm<1024, 2>, cudaFuncAttributeMaxDynamicSharedMemorySize, SMEM_SZ);
    cudaFuncSetAttribute(tc_gemm<2048, 3>, cudaFuncAttributeMaxDynamicSharedMemorySize, SMEM_SZ);

    __half *xTh, *Wqh, *Wkh, *Wvh, *Qh, *Kh, *Vh, *Ph;
    int8_t *xT8, *xTl8, *Wq8, *Wql8, *Wk8, *Wkl8, *Wv8, *Wvl8;
    int8_t *Q8, *Ql8, *K8, *Kl8, *V8, *Vl8, *P8, *Pl8;
    float* Sc;
    cudaGetSymbolAddress((void**)&xTh, g_xTh);
    cudaGetSymbolAddress((void**)&xT8, g_xT8);
    cudaGetSymbolAddress((void**)&xTl8, g_xTl8);
    cudaGetSymbolAddress((void**)&Wqh, g_Wqh);
    cudaGetSymbolAddress((void**)&Wq8, g_Wq8);
    cudaGetSymbolAddress((void**)&Wql8, g_Wql8);
    cudaGetSymbolAddress((void**)&Wkh, g_Wkh);
    cudaGetSymbolAddress((void**)&Wk8, g_Wk8);
    cudaGetSymbolAddress((void**)&Wkl8, g_Wkl8);
    cudaGetSymbolAddress((void**)&Wvh, g_Wvh);
    cudaGetSymbolAddress((void**)&Wv8, g_Wv8);
    cudaGetSymbolAddress((void**)&Wvl8, g_Wvl8);
    cudaGetSymbolAddress((void**)&Qh, g_Qh);
    cudaGetSymbolAddress((void**)&Q8, g_Q8);
    cudaGetSymbolAddress((void**)&Ql8, g_Ql8);
    cudaGetSymbolAddress((void**)&Kh, g_Kh);
    cudaGetSymbolAddress((void**)&K8, g_K8);
    cudaGetSymbolAddress((void**)&Kl8, g_Kl8);
    cudaGetSymbolAddress((void**)&Vh, g_Vh);
    cudaGetSymbolAddress((void**)&V8, g_V8);
    cudaGetSymbolAddress((void**)&Vl8, g_Vl8);
    cudaGetSymbolAddress((void**)&Ph, g_Ph);
    cudaGetSymbolAddress((void**)&P8, g_P8);
    cudaGetSymbolAddress((void**)&Pl8, g_Pl8);
    cudaGetSymbolAddress((void**)&Sc, g_S);

    const size_t SD = (size_t)S_ * D_;
    const size_t SS = (size_t)S_ * S_;

    // CSCALE = sAl*sBh = (M'A*2^-12/127)*(M'B/127)
    const float CS_PROJ = (8.0f / 4096.0f / 127.0f) * (0.03125f / 127.0f);
    const float CS_QK   = (4.0f / 4096.0f / 127.0f) * (4.0f / 127.0f);
    const float CS_AV   = (1.0f / 4096.0f / 127.0f) * (4.0f / 127.0f);

    // 1) operand preparation
    wsplit3_kernel<<<dim3(64, 3), 256>>>(Wq, Wk, Wv,
                                         Wqh, Wq8, Wql8,
                                         Wkh, Wk8, Wkl8,
                                         Wvh, Wv8, Wvl8);
    xpose_split_kernel<<<dim3(S_ / 32, D_ / 32, B_), 256>>>(x);

    // 2) projections
    tc_gemm<1024, 0><<<dim3(D_ / 64, S_ / 128, B_), 256, SMEM_SZ>>>(
        xTh, xT8, xTl8, SD, Wqh, Wq8, Wql8, 0, bq, CS_PROJ,
        nullptr, Qh, Q8, Ql8, SD, D_);
    tc_gemm<1024, 0><<<dim3(D_ / 64, S_ / 128, B_), 256, SMEM_SZ>>>(
        xTh, xT8, xTl8, SD, Wkh, Wk8, Wkl8, 0, bk, CS_PROJ,
        nullptr, Kh, K8, Kl8, SD, D_);
    tc_gemm<1024, 1><<<dim3(S_ / 64, D_ / 128, B_), 256, SMEM_SZ>>>(
        Wvh, Wv8, Wvl8, 0, xTh, xT8, xTl8, SD, bv, CS_PROJ,
        nullptr, Vh, V8, Vl8, SD, S_);

    // 3) scores
    tc_gemm<1024, 2><<<dim3(S_ / 64, S_ / 128, B_), 256, SMEM_SZ>>>(
        Qh, Q8, Ql8, SD, Kh, K8, Kl8, SD, nullptr, CS_QK,
        Sc, nullptr, nullptr, nullptr, SS, S_);

    // 4) softmax
    softmax_split_kernel<<<B_ * S_, 256>>>();

    // 5) out = P.V
    tc_gemm<2048, 3><<<dim3(D_ / 64, S_ / 128, B_), 256, SMEM_SZ>>>(
        Ph, P8, Pl8, SS, Vh, V8, Vl8, SD, nullptr, CS_AV,
        out, nullptr, nullptr, nullptr, SD, D_);
}